// round 5
// baseline (speedup 1.0000x reference)
#include <cuda_runtime.h>
#include <math.h>

#define Bb 32
#define NS 4096
#define Dd 256
#define Hh 4
#define Ll 6
#define NQ 512
#define NK 1024
#define DH 64
#define ATTN_SCALE 0.125f

// ---------------- scratch (static device globals; no allocation) -------------
__device__ float g_upd[Bb * NS * Dd];
__device__ float g_q[Bb * NQ * Dd];
__device__ float g_k[Bb * NK * Dd];
__device__ float g_Qp[Bb * NQ * Dd];
__device__ float g_Kp[Bb * NK * Dd];
__device__ float g_Vp[Bb * NK * Dd];
__device__ float g_ctx[Bb * NQ * Dd];
__device__ float g_h[Bb * NQ * Dd];
__device__ float g_t1[Bb * NQ * Dd];
__device__ float g_t2[Bb * NQ * Dd];

// ---------------- helpers ----------------------------------------------------
__device__ __forceinline__ float gelu_tanh(float x) {
    float x3 = x * x * x;
    return 0.5f * x * (1.f + tanhf(0.7978845608028654f * (x + 0.044715f * x3)));
}

__device__ __forceinline__ unsigned f2tf(float x) {
    unsigned r;
    asm("cvt.rna.tf32.f32 %0, %1;" : "=r"(r) : "f"(x));
    return r;
}

__device__ __forceinline__ void mma_tf32(float c[4], unsigned a0, unsigned a1,
                                         unsigned a2, unsigned a3,
                                         unsigned b0, unsigned b1) {
    asm volatile(
        "mma.sync.aligned.m16n8k8.row.col.f32.tf32.tf32.f32 "
        "{%0,%1,%2,%3}, {%4,%5,%6,%7}, {%8,%9}, {%0,%1,%2,%3};"
        : "+f"(c[0]), "+f"(c[1]), "+f"(c[2]), "+f"(c[3])
        : "r"(a0), "r"(a1), "r"(a2), "r"(a3), "r"(b0), "r"(b1));
}

// 64-thread-group sum reduction (4 groups of 64 per 256-thread block)
__device__ __forceinline__ float gsum64(float v, float* part, int warp, int lane, int grp) {
#pragma unroll
    for (int o = 16; o; o >>= 1) v += __shfl_xor_sync(0xffffffffu, v, o);
    if (lane == 0) part[warp] = v;
    __syncthreads();
    return part[2 * grp] + part[2 * grp + 1];
}

// ---------------- init: out = 0, upd = copy(src) ------------------------------
__global__ void k_init(const float* __restrict__ src, float* __restrict__ upd,
                       float* __restrict__ out, int n) {
    for (int i = blockIdx.x * blockDim.x + threadIdx.x; i < n; i += gridDim.x * blockDim.x) {
        out[i] = 0.f;
        upd[i] = src[i];
    }
}

// ---------------- gather + layernorm (4 rows/block, 64 thr/row, float4) -------
__global__ void k_gather_ln(const float* __restrict__ emb, const float* __restrict__ upd,
                            const int* __restrict__ idx, const float* __restrict__ sc,
                            const float* __restrict__ bi, float* __restrict__ out, int NR) {
    __shared__ float p1[8], p2[8];
    int tid = threadIdx.x, grp = tid >> 6, t = tid & 63, warp = tid >> 5, lane = tid & 31;
    int row = blockIdx.x * 4 + grp;
    int b = row / NR, i = row - b * NR;
    int id = idx[i];
    float4 e = ((const float4*)(emb + (size_t)id * Dd))[t];
    float4 u = ((const float4*)(upd + ((size_t)b * NS + id) * Dd))[t];
    float4 x = make_float4(e.x + u.x, e.y + u.y, e.z + u.z, e.w + u.w);
    float m = gsum64(x.x + x.y + x.z + x.w, p1, warp, lane, grp) * (1.f / 256.f);
    float4 dv = make_float4(x.x - m, x.y - m, x.z - m, x.w - m);
    float var = gsum64(dv.x * dv.x + dv.y * dv.y + dv.z * dv.z + dv.w * dv.w,
                       p2, warp, lane, grp) * (1.f / 256.f);
    float rs = rsqrtf(var + 1e-5f);
    float4 s4 = ((const float4*)sc)[t];
    float4 b4 = ((const float4*)bi)[t];
    ((float4*)(out + (size_t)row * Dd))[t] = make_float4(
        dv.x * rs * s4.x + b4.x, dv.y * rs * s4.y + b4.y,
        dv.z * rs * s4.z + b4.z, dv.w * rs * s4.w + b4.w);
}

// ---------------- plain layernorm (4 rows/block) ------------------------------
__global__ void k_ln(const float* __restrict__ x, const float* __restrict__ sc,
                     const float* __restrict__ bi, float* __restrict__ out) {
    __shared__ float p1[8], p2[8];
    int tid = threadIdx.x, grp = tid >> 6, t = tid & 63, warp = tid >> 5, lane = tid & 31;
    size_t row = blockIdx.x * 4 + grp;
    float4 v = ((const float4*)(x + row * Dd))[t];
    float m = gsum64(v.x + v.y + v.z + v.w, p1, warp, lane, grp) * (1.f / 256.f);
    float4 dv = make_float4(v.x - m, v.y - m, v.z - m, v.w - m);
    float var = gsum64(dv.x * dv.x + dv.y * dv.y + dv.z * dv.z + dv.w * dv.w,
                       p2, warp, lane, grp) * (1.f / 256.f);
    float rs = rsqrtf(var + 1e-5f);
    float4 s4 = ((const float4*)sc)[t];
    float4 b4 = ((const float4*)bi)[t];
    ((float4*)(out + row * Dd))[t] = make_float4(
        dv.x * rs * s4.x + b4.x, dv.y * rs * s4.y + b4.y,
        dv.z * rs * s4.z + b4.z, dv.w * rs * s4.w + b4.w);
}

// ---------------- fused double-LN + scatter-add -------------------------------
__global__ void k_dln_scatter(const float* __restrict__ hb, const float* __restrict__ f,
                              const float* __restrict__ os, const float* __restrict__ ob,
                              const float* __restrict__ es, const float* __restrict__ eb,
                              const int* __restrict__ qi,
                              float* __restrict__ upd, float* __restrict__ out) {
    __shared__ float p1[8], p2[8], p3[8], p4[8];
    int tid = threadIdx.x, grp = tid >> 6, t = tid & 63, warp = tid >> 5, lane = tid & 31;
    int row = blockIdx.x * 4 + grp;
    int b = row / NQ, q = row - b * NQ;
    float4 hv = ((const float4*)(hb + (size_t)row * Dd))[t];
    float4 fv = ((const float4*)(f + (size_t)row * Dd))[t];
    float4 x = make_float4(hv.x + fv.x, hv.y + fv.y, hv.z + fv.z, hv.w + fv.w);
    float m = gsum64(x.x + x.y + x.z + x.w, p1, warp, lane, grp) * (1.f / 256.f);
    float4 dv = make_float4(x.x - m, x.y - m, x.z - m, x.w - m);
    float var = gsum64(dv.x * dv.x + dv.y * dv.y + dv.z * dv.z + dv.w * dv.w,
                       p2, warp, lane, grp) * (1.f / 256.f);
    float rs = rsqrtf(var + 1e-5f);
    float4 s4 = ((const float4*)os)[t];
    float4 b4 = ((const float4*)ob)[t];
    float4 y = make_float4(dv.x * rs * s4.x + b4.x, dv.y * rs * s4.y + b4.y,
                           dv.z * rs * s4.z + b4.z, dv.w * rs * s4.w + b4.w);
    m = gsum64(y.x + y.y + y.z + y.w, p3, warp, lane, grp) * (1.f / 256.f);
    dv = make_float4(y.x - m, y.y - m, y.z - m, y.w - m);
    var = gsum64(dv.x * dv.x + dv.y * dv.y + dv.z * dv.z + dv.w * dv.w,
                 p4, warp, lane, grp) * (1.f / 256.f);
    rs = rsqrtf(var + 1e-5f);
    s4 = ((const float4*)es)[t];
    b4 = ((const float4*)eb)[t];
    float r0 = dv.x * rs * s4.x + b4.x, r1 = dv.y * rs * s4.y + b4.y;
    float r2 = dv.z * rs * s4.z + b4.z, r3 = dv.w * rs * s4.w + b4.w;
    int id = qi[q];
    size_t o = ((size_t)b * NS + id) * Dd + t * 4;
    atomicAdd(&upd[o + 0], r0); atomicAdd(&out[o + 0], r0);
    atomicAdd(&upd[o + 1], r1); atomicAdd(&out[o + 1], r1);
    atomicAdd(&upd[o + 2], r2); atomicAdd(&out[o + 2], r2);
    atomicAdd(&upd[o + 3], r3); atomicAdd(&out[o + 3], r3);
}

// ---------------- tf32 MMA GEMM with fragment-packed smem --------------------
// Block 128(M)x64(N), 8 warps, K chunk 32. Smem holds tf32 bits in frag order.
template <int ACT>
__global__ void __launch_bounds__(256, 2)
proj_mma(const float* __restrict__ A, const float* __restrict__ W,
         const float* __restrict__ bias, float* __restrict__ C) {
    __shared__ __align__(16) unsigned Asf[4096];  // (warp,k8,lane,reg)
    __shared__ __align__(16) unsigned Wsf[2048];  // (k8,jj,lane,(j&1)*2+r)
    int m0 = blockIdx.x * 128, n0 = blockIdx.y * 64;
    int tid = threadIdx.x, warp = tid >> 5, lane = tid & 31;
    int g = lane >> 2, tg = lane & 3;
    float acc[8][4];
#pragma unroll
    for (int j = 0; j < 8; j++)
#pragma unroll
        for (int i = 0; i < 4; i++) acc[j][i] = 0.f;

    for (int kc = 0; kc < 256; kc += 32) {
        __syncthreads();
        // A fill: 128x32 elements, fragment order
#pragma unroll
        for (int it = 0; it < 4; it++) {
            int i = tid + it * 256;
            int m = i >> 3, c4 = (i & 7) << 2;
            float4 v = *(const float4*)&A[(size_t)(m0 + m) * Dd + kc + c4];
            int w = m >> 4, rr = m & 15, gg = rr & 7, regrow = rr >> 3;
            float vv[4] = {v.x, v.y, v.z, v.w};
#pragma unroll
            for (int u = 0; u < 4; u++) {
                int k = c4 + u;
                int k8 = k >> 3, ki = k & 7, tt = ki & 3, regcol = ki >> 2;
                Asf[(((w << 2) | k8) << 7) + ((gg * 4 + tt) << 2) + regrow + 2 * regcol] = f2tf(vv[u]);
            }
        }
        // W fill: 32x64 elements, fragment order
#pragma unroll
        for (int it = 0; it < 2; it++) {
            int i = tid + it * 256;
            int r = i >> 4, c4 = (i & 15) << 2;
            float4 v = *(const float4*)&W[(size_t)(kc + r) * Dd + n0 + c4];
            int k8 = r >> 3, ki = r & 7, tt = ki & 3, rb = ki >> 2;
            float vv[4] = {v.x, v.y, v.z, v.w};
#pragma unroll
            for (int u = 0; u < 4; u++) {
                int n = c4 + u;
                int j = n >> 3, gg = n & 7, jj = j >> 1;
                Wsf[(((k8 << 2) | jj) << 7) + ((gg * 4 + tt) << 2) + ((j & 1) << 1) + rb] = f2tf(vv[u]);
            }
        }
        __syncthreads();
#pragma unroll
        for (int k8 = 0; k8 < 4; k8++) {
            uint4 av = *(const uint4*)&Asf[((warp * 4 + k8) * 32 + lane) * 4];
#pragma unroll
            for (int jj = 0; jj < 4; jj++) {
                uint4 bv = *(const uint4*)&Wsf[((k8 * 4 + jj) * 32 + lane) * 4];
                mma_tf32(acc[2 * jj], av.x, av.y, av.z, av.w, bv.x, bv.y);
                mma_tf32(acc[2 * jj + 1], av.x, av.y, av.z, av.w, bv.z, bv.w);
            }
        }
    }
#pragma unroll
    for (int j = 0; j < 8; j++) {
        int col = n0 + j * 8 + 2 * tg;
        float bv0 = bias ? bias[col] : 0.f;
        float bv1 = bias ? bias[col + 1] : 0.f;
        float v0 = acc[j][0] + bv0, v1 = acc[j][1] + bv1;
        float v2 = acc[j][2] + bv0, v3 = acc[j][3] + bv1;
        if (ACT) { v0 = gelu_tanh(v0); v1 = gelu_tanh(v1); v2 = gelu_tanh(v2); v3 = gelu_tanh(v3); }
        int r0 = m0 + warp * 16 + g;
        *(float2*)&C[(size_t)r0 * Dd + col] = make_float2(v0, v1);
        *(float2*)&C[(size_t)(r0 + 8) * Dd + col] = make_float2(v2, v3);
    }
}

// ---------------- fused flash attention (frag-packed tf32 MMA) ----------------
// grid (NQ/128, 1, B*H); block 256 (8 warps x 16-row q strips)
__global__ void __launch_bounds__(256, 2)
flash_attn(const float* __restrict__ Q, const float* __restrict__ K,
           const float* __restrict__ V, const float* __restrict__ mask,
           float* __restrict__ ctx) {
    extern __shared__ unsigned fsm[];
    unsigned* qsf = fsm;           // 8 warps * 8 k8 * 32 * 4 = 8192
    unsigned* ksf = fsm + 8192;    // 8 k8 * 4 jj * 32 * 4   = 4096
    unsigned* vsf = fsm + 12288;   // 4096
    unsigned* psf = fsm + 16384;   // 8192

    int bh = blockIdx.z;
    int b = bh >> 2, h = bh & 3;
    int q0 = blockIdx.x * 128;
    int tid = threadIdx.x, warp = tid >> 5, lane = tid & 31;
    int g = lane >> 2, tg = lane & 3;

    const float* Qg = Q + ((size_t)(b * NQ + q0)) * Dd + h * DH;
    const float* Kg = K + ((size_t)b * NK) * Dd + h * DH;
    const float* Vg = V + ((size_t)b * NK) * Dd + h * DH;

    // Q fill (fragment order, once)
#pragma unroll
    for (int it = 0; it < 8; it++) {
        int i = tid + it * 256;
        int m = i >> 4, c4 = (i & 15) << 2;
        float4 v = *(const float4*)&Qg[(size_t)m * Dd + c4];
        int w = m >> 4, rr = m & 15, gg = rr & 7, regrow = rr >> 3;
        float vv[4] = {v.x, v.y, v.z, v.w};
#pragma unroll
        for (int u = 0; u < 4; u++) {
            int c = c4 + u;
            int k8 = c >> 3, ki = c & 7, tt = ki & 3, regcol = ki >> 2;
            qsf[(((w << 3) | k8) << 7) + ((gg * 4 + tt) << 2) + regrow + 2 * regcol] = f2tf(vv[u]);
        }
    }

    float O[8][4];
#pragma unroll
    for (int j = 0; j < 8; j++)
#pragma unroll
        for (int i = 0; i < 4; i++) O[j][i] = 0.f;
    float m0r = -3.0e38f, m1r = -3.0e38f, l0 = 0.f, l1 = 0.f;

    const float* mrow0 = mask + (size_t)(q0 + warp * 16 + g) * NK;
    const float* mrow1 = mask + (size_t)(q0 + warp * 16 + g + 8) * NK;

    for (int kt = 0; kt < 16; kt++) {
        __syncthreads();
        int kbase = kt * 64;
        // K and V fill (fragment order)
#pragma unroll
        for (int it = 0; it < 4; it++) {
            int i = tid + it * 256;
            int r = i >> 4, c4 = (i & 15) << 2;
            float4 kv = *(const float4*)&Kg[(size_t)(kbase + r) * Dd + c4];
            float4 vv = *(const float4*)&Vg[(size_t)(kbase + r) * Dd + c4];
            // K: B-frag, n = token r, k = d
            int jK = r >> 3, gK = r & 7, jjK = jK >> 1;
            // V: B-frag, k = token r, n = d
            int k8V = r >> 3, kiV = r & 7, ttV = kiV & 3, rbV = kiV >> 2;
            float kk[4] = {kv.x, kv.y, kv.z, kv.w};
            float vl[4] = {vv.x, vv.y, vv.z, vv.w};
#pragma unroll
            for (int u = 0; u < 4; u++) {
                int c = c4 + u;
                int k8K = c >> 3, kiK = c & 7, ttK = kiK & 3, rbK = kiK >> 2;
                ksf[(((k8K << 2) | jjK) << 7) + ((gK * 4 + ttK) << 2) + ((jK & 1) << 1) + rbK] = f2tf(kk[u]);
                int jV = c >> 3, gV = c & 7, jjV = jV >> 1;
                vsf[(((k8V << 2) | jjV) << 7) + ((gV * 4 + ttV) << 2) + ((jV & 1) << 1) + rbV] = f2tf(vl[u]);
            }
        }
        __syncthreads();

        // S = Q @ K^T
        float s[8][4];
#pragma unroll
        for (int j = 0; j < 8; j++)
#pragma unroll
            for (int i = 0; i < 4; i++) s[j][i] = 0.f;
#pragma unroll
        for (int k8 = 0; k8 < 8; k8++) {
            uint4 av = *(const uint4*)&qsf[((warp * 8 + k8) * 32 + lane) * 4];
#pragma unroll
            for (int jj = 0; jj < 4; jj++) {
                uint4 bv = *(const uint4*)&ksf[((k8 * 4 + jj) * 32 + lane) * 4];
                mma_tf32(s[2 * jj], av.x, av.y, av.z, av.w, bv.x, bv.y);
                mma_tf32(s[2 * jj + 1], av.x, av.y, av.z, av.w, bv.z, bv.w);
            }
        }

        // scale + mask + row max
        float mx0 = -3.0e38f, mx1 = -3.0e38f;
#pragma unroll
        for (int j = 0; j < 8; j++) {
            int col = kbase + j * 8 + 2 * tg;
            float2 mk0 = *(const float2*)&mrow0[col];
            float2 mk1 = *(const float2*)&mrow1[col];
            s[j][0] = (mk0.x > 0.5f) ? s[j][0] * ATTN_SCALE : -1e9f;
            s[j][1] = (mk0.y > 0.5f) ? s[j][1] * ATTN_SCALE : -1e9f;
            s[j][2] = (mk1.x > 0.5f) ? s[j][2] * ATTN_SCALE : -1e9f;
            s[j][3] = (mk1.y > 0.5f) ? s[j][3] * ATTN_SCALE : -1e9f;
            mx0 = fmaxf(mx0, fmaxf(s[j][0], s[j][1]));
            mx1 = fmaxf(mx1, fmaxf(s[j][2], s[j][3]));
        }
        mx0 = fmaxf(mx0, __shfl_xor_sync(0xffffffffu, mx0, 1));
        mx0 = fmaxf(mx0, __shfl_xor_sync(0xffffffffu, mx0, 2));
        mx1 = fmaxf(mx1, __shfl_xor_sync(0xffffffffu, mx1, 1));
        mx1 = fmaxf(mx1, __shfl_xor_sync(0xffffffffu, mx1, 2));

        float mn0 = fmaxf(m0r, mx0), mn1 = fmaxf(m1r, mx1);
        float al0 = __expf(m0r - mn0), al1 = __expf(m1r - mn1);
        m0r = mn0; m1r = mn1;

        // exp + store P directly in PV-A-fragment layout
        float rs0 = 0.f, rs1 = 0.f;
        int rc = tg >> 1;
        int la = g * 4 + ((2 * tg) & 3);
        int lb = g * 4 + ((2 * tg + 1) & 3);
#pragma unroll
        for (int j = 0; j < 8; j++) {
            float p0 = __expf(s[j][0] - mn0), p1 = __expf(s[j][1] - mn0);
            float p2 = __expf(s[j][2] - mn1), p3 = __expf(s[j][3] - mn1);
            rs0 += p0 + p1; rs1 += p2 + p3;
            unsigned base = (unsigned)((warp * 8 + j) * 32) * 4;
            psf[base + la * 4 + 2 * rc]     = f2tf(p0);
            psf[base + lb * 4 + 2 * rc]     = f2tf(p1);
            psf[base + la * 4 + 2 * rc + 1] = f2tf(p2);
            psf[base + lb * 4 + 2 * rc + 1] = f2tf(p3);
        }
        rs0 += __shfl_xor_sync(0xffffffffu, rs0, 1);
        rs0 += __shfl_xor_sync(0xffffffffu, rs0, 2);
        rs1 += __shfl_xor_sync(0xffffffffu, rs1, 1);
        rs1 += __shfl_xor_sync(0xffffffffu, rs1, 2);
        l0 = l0 * al0 + rs0;
        l1 = l1 * al1 + rs1;
#pragma unroll
        for (int j = 0; j < 8; j++) {
            O[j][0] *= al0; O[j][1] *= al0; O[j][2] *= al1; O[j][3] *= al1;
        }
        __syncwarp();   // P frags (warp-local rows) visible

        // O += P @ V
#pragma unroll
        for (int k8 = 0; k8 < 8; k8++) {
            uint4 av = *(const uint4*)&psf[((warp * 8 + k8) * 32 + lane) * 4];
#pragma unroll
            for (int jj = 0; jj < 4; jj++) {
                uint4 bv = *(const uint4*)&vsf[((k8 * 4 + jj) * 32 + lane) * 4];
                mma_tf32(O[2 * jj], av.x, av.y, av.z, av.w, bv.x, bv.y);
                mma_tf32(O[2 * jj + 1], av.x, av.y, av.z, av.w, bv.z, bv.w);
            }
        }
    }

    float inv0 = 1.f / l0, inv1 = 1.f / l1;
    float* og = ctx + ((size_t)(b * NQ + q0)) * Dd + h * DH;
#pragma unroll
    for (int j = 0; j < 8; j++) {
        int col = j * 8 + 2 * tg;
        int r0 = warp * 16 + g;
        *(float2*)&og[(size_t)r0 * Dd + col] = make_float2(O[j][0] * inv0, O[j][1] * inv0);
        *(float2*)&og[(size_t)(r0 + 8) * Dd + col] = make_float2(O[j][2] * inv1, O[j][3] * inv1);
    }
}

// ---------------- launch ------------------------------------------------------
extern "C" void kernel_launch(void* const* d_in, const int* in_sizes, int n_in,
                              void* d_out, int out_size) {
    const float* upd_in = (const float*)d_in[0];
    const float* emb    = (const float*)d_in[1];
    const float* mask   = (const float*)d_in[2];
    const float* Wq     = (const float*)d_in[3];
    const float* Wk     = (const float*)d_in[4];
    const float* Wv     = (const float*)d_in[5];
    const float* Wo     = (const float*)d_in[6];
    const float* W1     = (const float*)d_in[7];
    const float* b1     = (const float*)d_in[8];
    const float* W2     = (const float*)d_in[9];
    const float* b2     = (const float*)d_in[10];
    const float* sys_s  = (const float*)d_in[11];
    const float* sys_b  = (const float*)d_in[12];
    const float* eff_s  = (const float*)d_in[13];
    const float* eff_b  = (const float*)d_in[14];
    const float* in_s   = (const float*)d_in[15];
    const float* in_b   = (const float*)d_in[16];
    const float* out_s  = (const float*)d_in[17];
    const float* out_b  = (const float*)d_in[18];
    const int*   qidx   = (const int*)d_in[19];
    const int*   kidx   = (const int*)d_in[20];
    float* out = (float*)d_out;

    float *upd, *qb, *kb, *Qp, *Kp, *Vp, *ctx, *hb, *t1, *t2;
    cudaGetSymbolAddress((void**)&upd, g_upd);
    cudaGetSymbolAddress((void**)&qb,  g_q);
    cudaGetSymbolAddress((void**)&kb,  g_k);
    cudaGetSymbolAddress((void**)&Qp,  g_Qp);
    cudaGetSymbolAddress((void**)&Kp,  g_Kp);
    cudaGetSymbolAddress((void**)&Vp,  g_Vp);
    cudaGetSymbolAddress((void**)&ctx, g_ctx);
    cudaGetSymbolAddress((void**)&hb,  g_h);
    cudaGetSymbolAddress((void**)&t1,  g_t1);
    cudaGetSymbolAddress((void**)&t2,  g_t2);

    cudaFuncSetAttribute(flash_attn, cudaFuncAttributeMaxDynamicSharedMemorySize, 98304);

    int n_upd = Bb * NS * Dd;
    k_init<<<8192, 256>>>(upd_in, upd, out, n_upd);

    for (int l = 0; l < Ll; l++) {
        const float* mask_l = mask + (size_t)l * NQ * NK;
        const int* qi = qidx + l * NQ;
        const int* ki = kidx + l * NK;

        k_gather_ln<<<Bb * NQ / 4, 256>>>(emb, upd, qi, sys_s, sys_b, qb, NQ);
        k_gather_ln<<<Bb * NK / 4, 256>>>(emb, upd, ki, sys_s, sys_b, kb, NK);

        proj_mma<0><<<dim3(128, 4), 256>>>(qb, Wq, nullptr, Qp);
        proj_mma<0><<<dim3(256, 4), 256>>>(kb, Wk, nullptr, Kp);
        proj_mma<0><<<dim3(256, 4), 256>>>(kb, Wv, nullptr, Vp);

        flash_attn<<<dim3(NQ / 128, 1, Bb * Hh), 256, 98304>>>(Qp, Kp, Vp, mask_l, ctx);

        proj_mma<0><<<dim3(128, 4), 256>>>(ctx, Wo, nullptr, t1);
        k_ln<<<Bb * NQ / 4, 256>>>(t1, in_s, in_b, hb);

        proj_mma<1><<<dim3(128, 4), 256>>>(hb, W1, b1, t1);
        proj_mma<0><<<dim3(128, 4), 256>>>(t1, W2, b2, t2);

        k_dln_scatter<<<Bb * NQ / 4, 256>>>(hb, t2, out_s, out_b, eff_s, eff_b,
                                            qi, upd, out);
    }
}

// round 6
// speedup vs baseline: 1.2406x; 1.2406x over previous
#include <cuda_runtime.h>
#include <math.h>

#define Bb 32
#define NS 4096
#define Dd 256
#define Hh 4
#define Ll 6
#define NQ 512
#define NK 1024
#define DH 64
#define ATTN_SCALE 0.125f

// ---------------- scratch (static device globals; no allocation) -------------
__device__ float g_upd[Bb * NS * Dd];
__device__ float g_q[Bb * NQ * Dd];
__device__ float g_k[Bb * NK * Dd];
__device__ float g_Qp[Bb * NQ * Dd];
__device__ float g_Kp[Bb * NK * Dd];
__device__ float g_Vp[Bb * NK * Dd];
__device__ float g_ctx[Bb * NQ * Dd];
__device__ float g_h[Bb * NQ * Dd];
__device__ float g_t1[Bb * NQ * Dd];
__device__ float g_t2[Bb * NQ * Dd];

// ---------------- helpers ----------------------------------------------------
__device__ __forceinline__ float gelu_tanh(float x) {
    float x3 = x * x * x;
    return 0.5f * x * (1.f + tanhf(0.7978845608028654f * (x + 0.044715f * x3)));
}

__device__ __forceinline__ unsigned f2tf(float x) {
    unsigned r;
    asm("cvt.rna.tf32.f32 %0, %1;" : "=r"(r) : "f"(x));
    return r;
}

__device__ __forceinline__ void mma_tf32(float c[4], unsigned a0, unsigned a1,
                                         unsigned a2, unsigned a3,
                                         unsigned b0, unsigned b1) {
    asm volatile(
        "mma.sync.aligned.m16n8k8.row.col.f32.tf32.tf32.f32 "
        "{%0,%1,%2,%3}, {%4,%5,%6,%7}, {%8,%9}, {%0,%1,%2,%3};"
        : "+f"(c[0]), "+f"(c[1]), "+f"(c[2]), "+f"(c[3])
        : "r"(a0), "r"(a1), "r"(a2), "r"(a3), "r"(b0), "r"(b1));
}

// 64-thread-group sum reduction (4 groups of 64 per 256-thread block)
__device__ __forceinline__ float gsum64(float v, float* part, int warp, int lane, int grp) {
#pragma unroll
    for (int o = 16; o; o >>= 1) v += __shfl_xor_sync(0xffffffffu, v, o);
    if (lane == 0) part[warp] = v;
    __syncthreads();
    return part[2 * grp] + part[2 * grp + 1];
}

// ---------------- init: out = 0, upd = copy(src) ------------------------------
__global__ void k_init(const float* __restrict__ src, float* __restrict__ upd,
                       float* __restrict__ out, int n) {
    for (int i = blockIdx.x * blockDim.x + threadIdx.x; i < n; i += gridDim.x * blockDim.x) {
        out[i] = 0.f;
        upd[i] = src[i];
    }
}

// ---------------- gather + layernorm (4 rows/block, 64 thr/row, float4) -------
__global__ void k_gather_ln(const float* __restrict__ emb, const float* __restrict__ upd,
                            const int* __restrict__ idx, const float* __restrict__ sc,
                            const float* __restrict__ bi, float* __restrict__ out, int NR) {
    __shared__ float p1[8], p2[8];
    int tid = threadIdx.x, grp = tid >> 6, t = tid & 63, warp = tid >> 5, lane = tid & 31;
    int row = blockIdx.x * 4 + grp;
    int b = row / NR, i = row - b * NR;
    int id = idx[i];
    float4 e = ((const float4*)(emb + (size_t)id * Dd))[t];
    float4 u = ((const float4*)(upd + ((size_t)b * NS + id) * Dd))[t];
    float4 x = make_float4(e.x + u.x, e.y + u.y, e.z + u.z, e.w + u.w);
    float m = gsum64(x.x + x.y + x.z + x.w, p1, warp, lane, grp) * (1.f / 256.f);
    float4 dv = make_float4(x.x - m, x.y - m, x.z - m, x.w - m);
    float var = gsum64(dv.x * dv.x + dv.y * dv.y + dv.z * dv.z + dv.w * dv.w,
                       p2, warp, lane, grp) * (1.f / 256.f);
    float rs = rsqrtf(var + 1e-5f);
    float4 s4 = ((const float4*)sc)[t];
    float4 b4 = ((const float4*)bi)[t];
    ((float4*)(out + (size_t)row * Dd))[t] = make_float4(
        dv.x * rs * s4.x + b4.x, dv.y * rs * s4.y + b4.y,
        dv.z * rs * s4.z + b4.z, dv.w * rs * s4.w + b4.w);
}

// ---------------- plain layernorm (4 rows/block) ------------------------------
__global__ void k_ln(const float* __restrict__ x, const float* __restrict__ sc,
                     const float* __restrict__ bi, float* __restrict__ out) {
    __shared__ float p1[8], p2[8];
    int tid = threadIdx.x, grp = tid >> 6, t = tid & 63, warp = tid >> 5, lane = tid & 31;
    size_t row = blockIdx.x * 4 + grp;
    float4 v = ((const float4*)(x + row * Dd))[t];
    float m = gsum64(v.x + v.y + v.z + v.w, p1, warp, lane, grp) * (1.f / 256.f);
    float4 dv = make_float4(v.x - m, v.y - m, v.z - m, v.w - m);
    float var = gsum64(dv.x * dv.x + dv.y * dv.y + dv.z * dv.z + dv.w * dv.w,
                       p2, warp, lane, grp) * (1.f / 256.f);
    float rs = rsqrtf(var + 1e-5f);
    float4 s4 = ((const float4*)sc)[t];
    float4 b4 = ((const float4*)bi)[t];
    ((float4*)(out + row * Dd))[t] = make_float4(
        dv.x * rs * s4.x + b4.x, dv.y * rs * s4.y + b4.y,
        dv.z * rs * s4.z + b4.z, dv.w * rs * s4.w + b4.w);
}

// ---------------- fused double-LN + scatter-add -------------------------------
__global__ void k_dln_scatter(const float* __restrict__ hb, const float* __restrict__ f,
                              const float* __restrict__ os, const float* __restrict__ ob,
                              const float* __restrict__ es, const float* __restrict__ eb,
                              const int* __restrict__ qi,
                              float* __restrict__ upd, float* __restrict__ out) {
    __shared__ float p1[8], p2[8], p3[8], p4[8];
    int tid = threadIdx.x, grp = tid >> 6, t = tid & 63, warp = tid >> 5, lane = tid & 31;
    int row = blockIdx.x * 4 + grp;
    int b = row / NQ, q = row - b * NQ;
    float4 hv = ((const float4*)(hb + (size_t)row * Dd))[t];
    float4 fv = ((const float4*)(f + (size_t)row * Dd))[t];
    float4 x = make_float4(hv.x + fv.x, hv.y + fv.y, hv.z + fv.z, hv.w + fv.w);
    float m = gsum64(x.x + x.y + x.z + x.w, p1, warp, lane, grp) * (1.f / 256.f);
    float4 dv = make_float4(x.x - m, x.y - m, x.z - m, x.w - m);
    float var = gsum64(dv.x * dv.x + dv.y * dv.y + dv.z * dv.z + dv.w * dv.w,
                       p2, warp, lane, grp) * (1.f / 256.f);
    float rs = rsqrtf(var + 1e-5f);
    float4 s4 = ((const float4*)os)[t];
    float4 b4 = ((const float4*)ob)[t];
    float4 y = make_float4(dv.x * rs * s4.x + b4.x, dv.y * rs * s4.y + b4.y,
                           dv.z * rs * s4.z + b4.z, dv.w * rs * s4.w + b4.w);
    m = gsum64(y.x + y.y + y.z + y.w, p3, warp, lane, grp) * (1.f / 256.f);
    dv = make_float4(y.x - m, y.y - m, y.z - m, y.w - m);
    var = gsum64(dv.x * dv.x + dv.y * dv.y + dv.z * dv.z + dv.w * dv.w,
                 p4, warp, lane, grp) * (1.f / 256.f);
    rs = rsqrtf(var + 1e-5f);
    s4 = ((const float4*)es)[t];
    b4 = ((const float4*)eb)[t];
    float r0 = dv.x * rs * s4.x + b4.x, r1 = dv.y * rs * s4.y + b4.y;
    float r2 = dv.z * rs * s4.z + b4.z, r3 = dv.w * rs * s4.w + b4.w;
    int id = qi[q];
    size_t o = ((size_t)b * NS + id) * Dd + t * 4;
    atomicAdd(&upd[o + 0], r0); atomicAdd(&out[o + 0], r0);
    atomicAdd(&upd[o + 1], r1); atomicAdd(&out[o + 1], r1);
    atomicAdd(&upd[o + 2], r2); atomicAdd(&out[o + 2], r2);
    atomicAdd(&upd[o + 3], r3); atomicAdd(&out[o + 3], r3);
}

// ---------------- tf32 MMA GEMM: C[M,256] = act(A @ W + bias) -----------------
// (R3-proven version) Block 128(M)x64(N), 8 warps, K chunk 32.
template <int ACT>
__global__ void proj_mma(const float* __restrict__ A, const float* __restrict__ W,
                         const float* __restrict__ bias, float* __restrict__ C) {
    __shared__ float As[128][36];
    __shared__ float Ws[32][72];
    int m0 = blockIdx.x * 128, n0 = blockIdx.y * 64;
    int tid = threadIdx.x, warp = tid >> 5, lane = tid & 31;
    int g = lane >> 2, tg = lane & 3;
    int mw = warp * 16;
    float acc[8][4];
#pragma unroll
    for (int j = 0; j < 8; j++)
#pragma unroll
        for (int i = 0; i < 4; i++) acc[j][i] = 0.f;

    for (int kc = 0; kc < 256; kc += 32) {
        __syncthreads();
#pragma unroll
        for (int i = tid; i < 1024; i += 256) {
            int r = i >> 3, c = (i & 7) << 2;
            float4 v = *(const float4*)&A[(size_t)(m0 + r) * Dd + kc + c];
            As[r][c] = v.x; As[r][c + 1] = v.y; As[r][c + 2] = v.z; As[r][c + 3] = v.w;
        }
#pragma unroll
        for (int i = tid; i < 512; i += 256) {
            int r = i >> 4, c = (i & 15) << 2;
            float4 v = *(const float4*)&W[(size_t)(kc + r) * Dd + n0 + c];
            Ws[r][c] = v.x; Ws[r][c + 1] = v.y; Ws[r][c + 2] = v.z; Ws[r][c + 3] = v.w;
        }
        __syncthreads();
#pragma unroll
        for (int k8 = 0; k8 < 4; k8++) {
            int kk = k8 * 8;
            unsigned a0 = f2tf(As[mw + g][kk + tg]);
            unsigned a1 = f2tf(As[mw + g + 8][kk + tg]);
            unsigned a2 = f2tf(As[mw + g][kk + tg + 4]);
            unsigned a3 = f2tf(As[mw + g + 8][kk + tg + 4]);
#pragma unroll
            for (int j = 0; j < 8; j++) {
                unsigned b0 = f2tf(Ws[kk + tg][j * 8 + g]);
                unsigned b1 = f2tf(Ws[kk + tg + 4][j * 8 + g]);
                mma_tf32(acc[j], a0, a1, a2, a3, b0, b1);
            }
        }
    }
#pragma unroll
    for (int j = 0; j < 8; j++) {
        int col = n0 + j * 8 + 2 * tg;
        float bv0 = bias ? bias[col] : 0.f;
        float bv1 = bias ? bias[col + 1] : 0.f;
        float v0 = acc[j][0] + bv0, v1 = acc[j][1] + bv1;
        float v2 = acc[j][2] + bv0, v3 = acc[j][3] + bv1;
        if (ACT) { v0 = gelu_tanh(v0); v1 = gelu_tanh(v1); v2 = gelu_tanh(v2); v3 = gelu_tanh(v3); }
        int r0 = m0 + mw + g;
        *(float2*)&C[(size_t)r0 * Dd + col] = make_float2(v0, v1);
        *(float2*)&C[(size_t)(r0 + 8) * Dd + col] = make_float2(v2, v3);
    }
}

// ---------------- fused flash attention (R3-proven) ---------------------------
// grid (NQ/128, 1, B*H); block 256 (8 warps, each warp owns a 16-row q strip)
__global__ void flash_attn(const float* __restrict__ Q, const float* __restrict__ K,
                           const float* __restrict__ V, const float* __restrict__ mask,
                           float* __restrict__ ctx) {
    extern __shared__ float sm[];
    float(*Qs)[68] = (float(*)[68])sm;                // 128 x 68
    float(*Ks)[68] = (float(*)[68])(sm + 8704);       // 64 x 68
    float(*Vs)[72] = (float(*)[72])(sm + 13056);      // 64 x 72
    float(*Ps)[68] = (float(*)[68])(sm + 17664);      // 128 x 68

    int bh = blockIdx.z;
    int b = bh >> 2, h = bh & 3;
    int q0 = blockIdx.x * 128;
    int tid = threadIdx.x, warp = tid >> 5, lane = tid & 31;
    int g = lane >> 2, tg = lane & 3;
    int mw = warp * 16;

    const float* Qg = Q + ((size_t)(b * NQ + q0)) * Dd + h * DH;
    const float* Kg = K + ((size_t)b * NK) * Dd + h * DH;
    const float* Vg = V + ((size_t)b * NK) * Dd + h * DH;

#pragma unroll
    for (int i = tid; i < 2048; i += 256) {
        int r = i >> 4, c = (i & 15) << 2;
        float4 v = *(const float4*)&Qg[(size_t)r * Dd + c];
        Qs[r][c] = v.x; Qs[r][c + 1] = v.y; Qs[r][c + 2] = v.z; Qs[r][c + 3] = v.w;
    }

    float O[8][4];
#pragma unroll
    for (int j = 0; j < 8; j++)
#pragma unroll
        for (int i = 0; i < 4; i++) O[j][i] = 0.f;
    float m0r = -3.0e38f, m1r = -3.0e38f, l0 = 0.f, l1 = 0.f;

    const float* mrow0 = mask + (size_t)(q0 + mw + g) * NK;
    const float* mrow1 = mask + (size_t)(q0 + mw + g + 8) * NK;

    for (int kt = 0; kt < 16; kt++) {
        __syncthreads();
        int kbase = kt * 64;
#pragma unroll
        for (int i = tid; i < 1024; i += 256) {
            int r = i >> 4, c = (i & 15) << 2;
            float4 kv = *(const float4*)&Kg[(size_t)(kbase + r) * Dd + c];
            Ks[r][c] = kv.x; Ks[r][c + 1] = kv.y; Ks[r][c + 2] = kv.z; Ks[r][c + 3] = kv.w;
            float4 vv = *(const float4*)&Vg[(size_t)(kbase + r) * Dd + c];
            Vs[r][c] = vv.x; Vs[r][c + 1] = vv.y; Vs[r][c + 2] = vv.z; Vs[r][c + 3] = vv.w;
        }
        __syncthreads();

        float s[8][4];
#pragma unroll
        for (int j = 0; j < 8; j++)
#pragma unroll
            for (int i = 0; i < 4; i++) s[j][i] = 0.f;
#pragma unroll
        for (int k8 = 0; k8 < 8; k8++) {
            int kk = k8 * 8;
            unsigned a0 = f2tf(Qs[mw + g][kk + tg]);
            unsigned a1 = f2tf(Qs[mw + g + 8][kk + tg]);
            unsigned a2 = f2tf(Qs[mw + g][kk + tg + 4]);
            unsigned a3 = f2tf(Qs[mw + g + 8][kk + tg + 4]);
#pragma unroll
            for (int j = 0; j < 8; j++) {
                unsigned b0 = f2tf(Ks[j * 8 + g][kk + tg]);
                unsigned b1 = f2tf(Ks[j * 8 + g][kk + tg + 4]);
                mma_tf32(s[j], a0, a1, a2, a3, b0, b1);
            }
        }

        float mx0 = -3.0e38f, mx1 = -3.0e38f;
#pragma unroll
        for (int j = 0; j < 8; j++) {
            int col = kbase + j * 8 + 2 * tg;
            float2 mk0 = *(const float2*)&mrow0[col];
            float2 mk1 = *(const float2*)&mrow1[col];
            s[j][0] = (mk0.x > 0.5f) ? s[j][0] * ATTN_SCALE : -1e9f;
            s[j][1] = (mk0.y > 0.5f) ? s[j][1] * ATTN_SCALE : -1e9f;
            s[j][2] = (mk1.x > 0.5f) ? s[j][2] * ATTN_SCALE : -1e9f;
            s[j][3] = (mk1.y > 0.5f) ? s[j][3] * ATTN_SCALE : -1e9f;
            mx0 = fmaxf(mx0, fmaxf(s[j][0], s[j][1]));
            mx1 = fmaxf(mx1, fmaxf(s[j][2], s[j][3]));
        }
        mx0 = fmaxf(mx0, __shfl_xor_sync(0xffffffffu, mx0, 1));
        mx0 = fmaxf(mx0, __shfl_xor_sync(0xffffffffu, mx0, 2));
        mx1 = fmaxf(mx1, __shfl_xor_sync(0xffffffffu, mx1, 1));
        mx1 = fmaxf(mx1, __shfl_xor_sync(0xffffffffu, mx1, 2));

        float mn0 = fmaxf(m0r, mx0), mn1 = fmaxf(m1r, mx1);
        float al0 = __expf(m0r - mn0), al1 = __expf(m1r - mn1);
        m0r = mn0; m1r = mn1;

        float rs0 = 0.f, rs1 = 0.f;
#pragma unroll
        for (int j = 0; j < 8; j++) {
            float p0 = __expf(s[j][0] - mn0), p1 = __expf(s[j][1] - mn0);
            float p2 = __expf(s[j][2] - mn1), p3 = __expf(s[j][3] - mn1);
            rs0 += p0 + p1; rs1 += p2 + p3;
            int col = j * 8 + 2 * tg;
            Ps[mw + g][col] = p0;     Ps[mw + g][col + 1] = p1;
            Ps[mw + g + 8][col] = p2; Ps[mw + g + 8][col + 1] = p3;
        }
        rs0 += __shfl_xor_sync(0xffffffffu, rs0, 1);
        rs0 += __shfl_xor_sync(0xffffffffu, rs0, 2);
        rs1 += __shfl_xor_sync(0xffffffffu, rs1, 1);
        rs1 += __shfl_xor_sync(0xffffffffu, rs1, 2);
        l0 = l0 * al0 + rs0;
        l1 = l1 * al1 + rs1;
#pragma unroll
        for (int j = 0; j < 8; j++) {
            O[j][0] *= al0; O[j][1] *= al0; O[j][2] *= al1; O[j][3] *= al1;
        }
        __syncwarp();

#pragma unroll
        for (int k8 = 0; k8 < 8; k8++) {
            int kk = k8 * 8;
            unsigned a0 = f2tf(Ps[mw + g][kk + tg]);
            unsigned a1 = f2tf(Ps[mw + g + 8][kk + tg]);
            unsigned a2 = f2tf(Ps[mw + g][kk + tg + 4]);
            unsigned a3 = f2tf(Ps[mw + g + 8][kk + tg + 4]);
#pragma unroll
            for (int j = 0; j < 8; j++) {
                unsigned b0 = f2tf(Vs[kk + tg][j * 8 + g]);
                unsigned b1 = f2tf(Vs[kk + tg + 4][j * 8 + g]);
                mma_tf32(O[j], a0, a1, a2, a3, b0, b1);
            }
        }
    }

    float inv0 = 1.f / l0, inv1 = 1.f / l1;
    float* og = ctx + ((size_t)(b * NQ + q0)) * Dd + h * DH;
#pragma unroll
    for (int j = 0; j < 8; j++) {
        int col = j * 8 + 2 * tg;
        *(float2*)&og[(size_t)(mw + g) * Dd + col] = make_float2(O[j][0] * inv0, O[j][1] * inv0);
        *(float2*)&og[(size_t)(mw + g + 8) * Dd + col] = make_float2(O[j][2] * inv1, O[j][3] * inv1);
    }
}

// ---------------- launch ------------------------------------------------------
extern "C" void kernel_launch(void* const* d_in, const int* in_sizes, int n_in,
                              void* d_out, int out_size) {
    const float* upd_in = (const float*)d_in[0];
    const float* emb    = (const float*)d_in[1];
    const float* mask   = (const float*)d_in[2];
    const float* Wq     = (const float*)d_in[3];
    const float* Wk     = (const float*)d_in[4];
    const float* Wv     = (const float*)d_in[5];
    const float* Wo     = (const float*)d_in[6];
    const float* W1     = (const float*)d_in[7];
    const float* b1     = (const float*)d_in[8];
    const float* W2     = (const float*)d_in[9];
    const float* b2     = (const float*)d_in[10];
    const float* sys_s  = (const float*)d_in[11];
    const float* sys_b  = (const float*)d_in[12];
    const float* eff_s  = (const float*)d_in[13];
    const float* eff_b  = (const float*)d_in[14];
    const float* in_s   = (const float*)d_in[15];
    const float* in_b   = (const float*)d_in[16];
    const float* out_s  = (const float*)d_in[17];
    const float* out_b  = (const float*)d_in[18];
    const int*   qidx   = (const int*)d_in[19];
    const int*   kidx   = (const int*)d_in[20];
    float* out = (float*)d_out;

    float *upd, *qb, *kb, *Qp, *Kp, *Vp, *ctx, *hb, *t1, *t2;
    cudaGetSymbolAddress((void**)&upd, g_upd);
    cudaGetSymbolAddress((void**)&qb,  g_q);
    cudaGetSymbolAddress((void**)&kb,  g_k);
    cudaGetSymbolAddress((void**)&Qp,  g_Qp);
    cudaGetSymbolAddress((void**)&Kp,  g_Kp);
    cudaGetSymbolAddress((void**)&Vp,  g_Vp);
    cudaGetSymbolAddress((void**)&ctx, g_ctx);
    cudaGetSymbolAddress((void**)&hb,  g_h);
    cudaGetSymbolAddress((void**)&t1,  g_t1);
    cudaGetSymbolAddress((void**)&t2,  g_t2);

    cudaFuncSetAttribute(flash_attn, cudaFuncAttributeMaxDynamicSharedMemorySize, 105472);

    int n_upd = Bb * NS * Dd;
    k_init<<<8192, 256>>>(upd_in, upd, out, n_upd);

    for (int l = 0; l < Ll; l++) {
        const float* mask_l = mask + (size_t)l * NQ * NK;
        const int* qi = qidx + l * NQ;
        const int* ki = kidx + l * NK;

        k_gather_ln<<<Bb * NQ / 4, 256>>>(emb, upd, qi, sys_s, sys_b, qb, NQ);
        k_gather_ln<<<Bb * NK / 4, 256>>>(emb, upd, ki, sys_s, sys_b, kb, NK);

        proj_mma<0><<<dim3(128, 4), 256>>>(qb, Wq, nullptr, Qp);
        proj_mma<0><<<dim3(256, 4), 256>>>(kb, Wk, nullptr, Kp);
        proj_mma<0><<<dim3(256, 4), 256>>>(kb, Wv, nullptr, Vp);

        flash_attn<<<dim3(NQ / 128, 1, Bb * Hh), 256, 105472>>>(Qp, Kp, Vp, mask_l, ctx);

        proj_mma<0><<<dim3(128, 4), 256>>>(ctx, Wo, nullptr, t1);
        k_ln<<<Bb * NQ / 4, 256>>>(t1, in_s, in_b, hb);

        proj_mma<1><<<dim3(128, 4), 256>>>(hb, W1, b1, t1);
        proj_mma<0><<<dim3(128, 4), 256>>>(t1, W2, b2, t2);

        k_dln_scatter<<<Bb * NQ / 4, 256>>>(hb, t2, out_s, out_b, eff_s, eff_b,
                                            qi, upd, out);
    }
}

// round 8
// speedup vs baseline: 2.2146x; 1.7850x over previous
#include <cuda_runtime.h>
#include <cuda_fp16.h>
#include <math.h>

#define Bb 32
#define NS 4096
#define Dd 256
#define Hh 4
#define Ll 6
#define NQ 512
#define NK 1024
#define DH 64
#define ATTN_SCALE 0.125f

// ---------------- scratch (static device globals; no allocation) -------------
__device__ float  g_upd[Bb * NS * Dd];
__device__ float  g_hb [Bb * NQ * Dd];   // h (fp32 residual)
__device__ float  g_t1f[Bb * NQ * Dd];   // Wo out (fp32, pre-LN)
__device__ float  g_t2 [Bb * NQ * Dd];   // ffn out (fp32)
__device__ __half g_qh [Bb * NQ * Dd];
__device__ __half g_kh [Bb * NK * Dd];
__device__ __half g_Qh [Bb * NQ * Dd];
__device__ __half g_Kh [Bb * NK * Dd];
__device__ __half g_Vh [Bb * NK * Dd];
__device__ __half g_ctxh[Bb * NQ * Dd];
__device__ __half g_hh [Bb * NQ * Dd];
__device__ __half g_t1h[Bb * NQ * Dd];
__device__ __half g_WT [6 * Dd * Dd];    // transposed half weights [n][k]

// ---------------- helpers ----------------------------------------------------
__device__ __forceinline__ float gelu_tanh(float x) {
    float x3 = x * x * x;
    return 0.5f * x * (1.f + tanhf(0.7978845608028654f * (x + 0.044715f * x3)));
}

__device__ __forceinline__ unsigned h2u(__half2 h) {
    return *reinterpret_cast<unsigned*>(&h);
}

__device__ __forceinline__ void mma_f16(float c[4], unsigned a0, unsigned a1,
                                        unsigned a2, unsigned a3,
                                        unsigned b0, unsigned b1) {
    asm volatile(
        "mma.sync.aligned.m16n8k16.row.col.f32.f16.f16.f32 "
        "{%0,%1,%2,%3}, {%4,%5,%6,%7}, {%8,%9}, {%0,%1,%2,%3};"
        : "+f"(c[0]), "+f"(c[1]), "+f"(c[2]), "+f"(c[3])
        : "r"(a0), "r"(a1), "r"(a2), "r"(a3), "r"(b0), "r"(b1));
}

__device__ __forceinline__ float gsum64(float v, float* part, int warp, int lane, int grp) {
#pragma unroll
    for (int o = 16; o; o >>= 1) v += __shfl_xor_sync(0xffffffffu, v, o);
    if (lane == 0) part[warp] = v;
    __syncthreads();
    return part[2 * grp] + part[2 * grp + 1];
}

// ---------------- init: out = 0, upd = copy(src) ------------------------------
__global__ void k_init(const float* __restrict__ src, float* __restrict__ upd,
                       float* __restrict__ out, int n) {
    for (int i = blockIdx.x * blockDim.x + threadIdx.x; i < n; i += gridDim.x * blockDim.x) {
        out[i] = 0.f;
        upd[i] = src[i];
    }
}

// ---------------- weight transpose + fp16 convert (once per launch) -----------
__global__ void k_prep(const float* __restrict__ Wq, const float* __restrict__ Wk,
                       const float* __restrict__ Wv, const float* __restrict__ Wo,
                       const float* __restrict__ W1, const float* __restrict__ W2,
                       __half* __restrict__ WT) {
    __shared__ float tile[32][33];
    int w = blockIdx.z;
    const float* W = (w == 0) ? Wq : (w == 1) ? Wk : (w == 2) ? Wv
                   : (w == 3) ? Wo : (w == 4) ? W1 : W2;
    int k0 = blockIdx.x * 32, n0 = blockIdx.y * 32;
    int tx = threadIdx.x, ty = threadIdx.y;   // (32, 8)
#pragma unroll
    for (int r = 0; r < 32; r += 8)
        tile[ty + r][tx] = W[(size_t)(k0 + ty + r) * Dd + n0 + tx];
    __syncthreads();
#pragma unroll
    for (int r = 0; r < 32; r += 8)
        WT[(size_t)w * Dd * Dd + (size_t)(n0 + ty + r) * Dd + k0 + tx] =
            __float2half(tile[tx][ty + r]);
}

// ---------------- gather + layernorm -> half (4 rows/block, 64 thr/row) ------
__global__ void k_gather_ln(const float* __restrict__ emb, const float* __restrict__ upd,
                            const int* __restrict__ idx, const float* __restrict__ sc,
                            const float* __restrict__ bi, __half* __restrict__ out, int NR) {
    __shared__ float p1[8], p2[8];
    int tid = threadIdx.x, grp = tid >> 6, t = tid & 63, warp = tid >> 5, lane = tid & 31;
    int row = blockIdx.x * 4 + grp;
    int b = row / NR, i = row - b * NR;
    int id = idx[i];
    float4 e = ((const float4*)(emb + (size_t)id * Dd))[t];
    float4 u = ((const float4*)(upd + ((size_t)b * NS + id) * Dd))[t];
    float4 x = make_float4(e.x + u.x, e.y + u.y, e.z + u.z, e.w + u.w);
    float m = gsum64(x.x + x.y + x.z + x.w, p1, warp, lane, grp) * (1.f / 256.f);
    float4 dv = make_float4(x.x - m, x.y - m, x.z - m, x.w - m);
    float var = gsum64(dv.x * dv.x + dv.y * dv.y + dv.z * dv.z + dv.w * dv.w,
                       p2, warp, lane, grp) * (1.f / 256.f);
    float rs = rsqrtf(var + 1e-5f);
    float4 s4 = ((const float4*)sc)[t];
    float4 b4 = ((const float4*)bi)[t];
    __half2 h0 = __floats2half2_rn(dv.x * rs * s4.x + b4.x, dv.y * rs * s4.y + b4.y);
    __half2 h1 = __floats2half2_rn(dv.z * rs * s4.z + b4.z, dv.w * rs * s4.w + b4.w);
    uint2 pk; pk.x = h2u(h0); pk.y = h2u(h1);
    *(uint2*)&out[(size_t)row * Dd + 4 * t] = pk;
}

// ---------------- layernorm -> fp32 + half (4 rows/block) ---------------------
__global__ void k_ln(const float* __restrict__ x, const float* __restrict__ sc,
                     const float* __restrict__ bi, float* __restrict__ outf,
                     __half* __restrict__ outh) {
    __shared__ float p1[8], p2[8];
    int tid = threadIdx.x, grp = tid >> 6, t = tid & 63, warp = tid >> 5, lane = tid & 31;
    size_t row = blockIdx.x * 4 + grp;
    float4 v = ((const float4*)(x + row * Dd))[t];
    float m = gsum64(v.x + v.y + v.z + v.w, p1, warp, lane, grp) * (1.f / 256.f);
    float4 dv = make_float4(v.x - m, v.y - m, v.z - m, v.w - m);
    float var = gsum64(dv.x * dv.x + dv.y * dv.y + dv.z * dv.z + dv.w * dv.w,
                       p2, warp, lane, grp) * (1.f / 256.f);
    float rs = rsqrtf(var + 1e-5f);
    float4 s4 = ((const float4*)sc)[t];
    float4 b4 = ((const float4*)bi)[t];
    float4 y = make_float4(dv.x * rs * s4.x + b4.x, dv.y * rs * s4.y + b4.y,
                           dv.z * rs * s4.z + b4.z, dv.w * rs * s4.w + b4.w);
    ((float4*)(outf + row * Dd))[t] = y;
    __half2 h0 = __floats2half2_rn(y.x, y.y);
    __half2 h1 = __floats2half2_rn(y.z, y.w);
    uint2 pk; pk.x = h2u(h0); pk.y = h2u(h1);
    *(uint2*)&outh[row * Dd + 4 * t] = pk;
}

// ---------------- fused double-LN + scatter-add -------------------------------
__global__ void k_dln_scatter(const float* __restrict__ hb, const float* __restrict__ f,
                              const float* __restrict__ os, const float* __restrict__ ob,
                              const float* __restrict__ es, const float* __restrict__ eb,
                              const int* __restrict__ qi,
                              float* __restrict__ upd, float* __restrict__ out) {
    __shared__ float p1[8], p2[8], p3[8], p4[8];
    int tid = threadIdx.x, grp = tid >> 6, t = tid & 63, warp = tid >> 5, lane = tid & 31;
    int row = blockIdx.x * 4 + grp;
    int b = row / NQ, q = row - b * NQ;
    float4 hv = ((const float4*)(hb + (size_t)row * Dd))[t];
    float4 fv = ((const float4*)(f + (size_t)row * Dd))[t];
    float4 x = make_float4(hv.x + fv.x, hv.y + fv.y, hv.z + fv.z, hv.w + fv.w);
    float m = gsum64(x.x + x.y + x.z + x.w, p1, warp, lane, grp) * (1.f / 256.f);
    float4 dv = make_float4(x.x - m, x.y - m, x.z - m, x.w - m);
    float var = gsum64(dv.x * dv.x + dv.y * dv.y + dv.z * dv.z + dv.w * dv.w,
                       p2, warp, lane, grp) * (1.f / 256.f);
    float rs = rsqrtf(var + 1e-5f);
    float4 s4 = ((const float4*)os)[t];
    float4 b4 = ((const float4*)ob)[t];
    float4 y = make_float4(dv.x * rs * s4.x + b4.x, dv.y * rs * s4.y + b4.y,
                           dv.z * rs * s4.z + b4.z, dv.w * rs * s4.w + b4.w);
    m = gsum64(y.x + y.y + y.z + y.w, p3, warp, lane, grp) * (1.f / 256.f);
    dv = make_float4(y.x - m, y.y - m, y.z - m, y.w - m);
    var = gsum64(dv.x * dv.x + dv.y * dv.y + dv.z * dv.z + dv.w * dv.w,
                 p4, warp, lane, grp) * (1.f / 256.f);
    rs = rsqrtf(var + 1e-5f);
    s4 = ((const float4*)es)[t];
    b4 = ((const float4*)eb)[t];
    float r0 = dv.x * rs * s4.x + b4.x, r1 = dv.y * rs * s4.y + b4.y;
    float r2 = dv.z * rs * s4.z + b4.z, r3 = dv.w * rs * s4.w + b4.w;
    int id = qi[q];
    size_t o = ((size_t)b * NS + id) * Dd + t * 4;
    atomicAdd(&upd[o + 0], r0); atomicAdd(&out[o + 0], r0);
    atomicAdd(&upd[o + 1], r1); atomicAdd(&out[o + 1], r1);
    atomicAdd(&upd[o + 2], r2); atomicAdd(&out[o + 2], r2);
    atomicAdd(&upd[o + 3], r3); atomicAdd(&out[o + 3], r3);
}

// ---------------- fp16 MMA GEMM: C = act(A @ WT^T + bias) ---------------------
// A: [M][256] half, WT: [256 n][256 k] half (pre-transposed).
// Block 128(M)x64(N), 8 warps, K chunk 64, m16n8k16.
template <int ACT, int HOUT>
__global__ void __launch_bounds__(256)
proj_h(const __half* __restrict__ A, const __half* __restrict__ WT,
       const float* __restrict__ bias, __half* __restrict__ Ch,
       float* __restrict__ Cf) {
    __shared__ __align__(16) __half As[128 * 72];
    __shared__ __align__(16) __half Ws[64 * 72];
    int m0 = blockIdx.x * 128, n0 = blockIdx.y * 64;
    int tid = threadIdx.x, warp = tid >> 5, lane = tid & 31;
    int g = lane >> 2, tg = lane & 3;
    int mw = warp * 16;
    float acc[8][4];
#pragma unroll
    for (int j = 0; j < 8; j++)
#pragma unroll
        for (int i = 0; i < 4; i++) acc[j][i] = 0.f;

    for (int kc = 0; kc < 256; kc += 64) {
        __syncthreads();
#pragma unroll
        for (int it = 0; it < 4; it++) {
            int i = tid + it * 256;
            int r = i >> 3, c8 = (i & 7) << 3;
            *(uint4*)&As[r * 72 + c8] = *(const uint4*)&A[(size_t)(m0 + r) * Dd + kc + c8];
        }
#pragma unroll
        for (int it = 0; it < 2; it++) {
            int i = tid + it * 256;
            int r = i >> 3, c8 = (i & 7) << 3;
            *(uint4*)&Ws[r * 72 + c8] = *(const uint4*)&WT[(size_t)(n0 + r) * Dd + kc + c8];
        }
        __syncthreads();
#pragma unroll
        for (int k16 = 0; k16 < 4; k16++) {
            int kk = k16 * 16;
            unsigned a0 = *(const unsigned*)&As[(mw + g) * 72 + kk + 2 * tg];
            unsigned a1 = *(const unsigned*)&As[(mw + g + 8) * 72 + kk + 2 * tg];
            unsigned a2 = *(const unsigned*)&As[(mw + g) * 72 + kk + 2 * tg + 8];
            unsigned a3 = *(const unsigned*)&As[(mw + g + 8) * 72 + kk + 2 * tg + 8];
#pragma unroll
            for (int j = 0; j < 8; j++) {
                unsigned b0 = *(const unsigned*)&Ws[(j * 8 + g) * 72 + kk + 2 * tg];
                unsigned b1 = *(const unsigned*)&Ws[(j * 8 + g) * 72 + kk + 2 * tg + 8];
                mma_f16(acc[j], a0, a1, a2, a3, b0, b1);
            }
        }
    }
#pragma unroll
    for (int j = 0; j < 8; j++) {
        int col = n0 + j * 8 + 2 * tg;
        float bv0 = bias ? bias[col] : 0.f;
        float bv1 = bias ? bias[col + 1] : 0.f;
        float v0 = acc[j][0] + bv0, v1 = acc[j][1] + bv1;   // row mw+g
        float v2 = acc[j][2] + bv0, v3 = acc[j][3] + bv1;   // row mw+g+8
        if (ACT) { v0 = gelu_tanh(v0); v1 = gelu_tanh(v1); v2 = gelu_tanh(v2); v3 = gelu_tanh(v3); }
        int r0 = m0 + mw + g;
        if (HOUT) {
            __half2 hA = __floats2half2_rn(v0, v1);
            __half2 hB = __floats2half2_rn(v2, v3);
            *(unsigned*)&Ch[(size_t)r0 * Dd + col] = h2u(hA);
            *(unsigned*)&Ch[(size_t)(r0 + 8) * Dd + col] = h2u(hB);
        } else {
            *(float2*)&Cf[(size_t)r0 * Dd + col] = make_float2(v0, v1);
            *(float2*)&Cf[(size_t)(r0 + 8) * Dd + col] = make_float2(v2, v3);
        }
    }
}

// ---------------- fused flash attention (fp16 MMA, online softmax) ------------
// grid (NQ/128, 1, B*H); block 256 (8 warps x 16-row q strips)
__global__ void __launch_bounds__(256)
flash_attn(const __half* __restrict__ Q, const __half* __restrict__ K,
           const __half* __restrict__ V, const float* __restrict__ mask,
           __half* __restrict__ ctx) {
    extern __shared__ __half hsm[];
    __half* Qs = hsm;                // 128*72
    __half* Ks = hsm + 9216;         // 64*72
    __half* Vs = hsm + 13824;        // 64*72
    __half* Ps = hsm + 18432;        // 128*72  (total 27648 halves = 55296 B)

    int bh = blockIdx.z;
    int b = bh >> 2, h = bh & 3;
    int q0 = blockIdx.x * 128;
    int tid = threadIdx.x, warp = tid >> 5, lane = tid & 31;
    int g = lane >> 2, tg = lane & 3;
    int mw = warp * 16;

    const __half* Qg = Q + ((size_t)(b * NQ + q0)) * Dd + h * DH;
    const __half* Kg = K + ((size_t)b * NK) * Dd + h * DH;
    const __half* Vg = V + ((size_t)b * NK) * Dd + h * DH;

#pragma unroll
    for (int it = 0; it < 4; it++) {
        int i = tid + it * 256;
        int r = i >> 3, c8 = (i & 7) << 3;
        *(uint4*)&Qs[r * 72 + c8] = *(const uint4*)&Qg[(size_t)r * Dd + c8];
    }

    float O[8][4];
#pragma unroll
    for (int j = 0; j < 8; j++)
#pragma unroll
        for (int i = 0; i < 4; i++) O[j][i] = 0.f;
    float m0r = -3.0e38f, m1r = -3.0e38f, l0 = 0.f, l1 = 0.f;

    const float* mrow0 = mask + (size_t)(q0 + mw + g) * NK;       // row mw+g
    const float* mrow1 = mask + (size_t)(q0 + mw + g + 8) * NK;   // row mw+g+8

    for (int kt = 0; kt < 16; kt++) {
        __syncthreads();
        int kbase = kt * 64;
#pragma unroll
        for (int it = 0; it < 2; it++) {
            int i = tid + it * 256;
            int r = i >> 3, c8 = (i & 7) << 3;
            *(uint4*)&Ks[r * 72 + c8] = *(const uint4*)&Kg[(size_t)(kbase + r) * Dd + c8];
        }
#pragma unroll
        for (int it = 0; it < 2; it++) {
            int i = tid + it * 256;
            int r = i >> 3, c8 = (i & 7) << 3;
            *(uint4*)&Vs[r * 72 + c8] = *(const uint4*)&Vg[(size_t)(kbase + r) * Dd + c8];
        }
        __syncthreads();

        // S = Q @ K^T  (K rows are n-major: direct B-frag LDS)
        float s[8][4];
#pragma unroll
        for (int j = 0; j < 8; j++)
#pragma unroll
            for (int i = 0; i < 4; i++) s[j][i] = 0.f;
#pragma unroll
        for (int k16 = 0; k16 < 4; k16++) {
            int kk = k16 * 16;
            unsigned a0 = *(const unsigned*)&Qs[(mw + g) * 72 + kk + 2 * tg];
            unsigned a1 = *(const unsigned*)&Qs[(mw + g + 8) * 72 + kk + 2 * tg];
            unsigned a2 = *(const unsigned*)&Qs[(mw + g) * 72 + kk + 2 * tg + 8];
            unsigned a3 = *(const unsigned*)&Qs[(mw + g + 8) * 72 + kk + 2 * tg + 8];
#pragma unroll
            for (int j = 0; j < 8; j++) {
                unsigned b0 = *(const unsigned*)&Ks[(j * 8 + g) * 72 + kk + 2 * tg];
                unsigned b1 = *(const unsigned*)&Ks[(j * 8 + g) * 72 + kk + 2 * tg + 8];
                mma_f16(s[j], a0, a1, a2, a3, b0, b1);
            }
        }

        // scale + mask + row max   (c0,c1: row g cols 2tg,2tg+1; c2,c3: row g+8)
        float mx0 = -3.0e38f, mx1 = -3.0e38f;
#pragma unroll
        for (int j = 0; j < 8; j++) {
            int col = kbase + j * 8 + 2 * tg;
            float2 mk0 = *(const float2*)&mrow0[col];
            float2 mk1 = *(const float2*)&mrow1[col];
            s[j][0] = (mk0.x > 0.5f) ? s[j][0] * ATTN_SCALE : -1e9f;
            s[j][1] = (mk0.y > 0.5f) ? s[j][1] * ATTN_SCALE : -1e9f;
            s[j][2] = (mk1.x > 0.5f) ? s[j][2] * ATTN_SCALE : -1e9f;
            s[j][3] = (mk1.y > 0.5f) ? s[j][3] * ATTN_SCALE : -1e9f;
            mx0 = fmaxf(mx0, fmaxf(s[j][0], s[j][1]));
            mx1 = fmaxf(mx1, fmaxf(s[j][2], s[j][3]));
        }
        mx0 = fmaxf(mx0, __shfl_xor_sync(0xffffffffu, mx0, 1));
        mx0 = fmaxf(mx0, __shfl_xor_sync(0xffffffffu, mx0, 2));
        mx1 = fmaxf(mx1, __shfl_xor_sync(0xffffffffu, mx1, 1));
        mx1 = fmaxf(mx1, __shfl_xor_sync(0xffffffffu, mx1, 2));

        float mn0 = fmaxf(m0r, mx0), mn1 = fmaxf(m1r, mx1);
        float al0 = __expf(m0r - mn0), al1 = __expf(m1r - mn1);
        m0r = mn0; m1r = mn1;

        // exp + store P as half2 (directly A-frag compatible layout)
        float rs0 = 0.f, rs1 = 0.f;
#pragma unroll
        for (int j = 0; j < 8; j++) {
            float p0 = __expf(s[j][0] - mn0), p1 = __expf(s[j][1] - mn0);
            float p2 = __expf(s[j][2] - mn1), p3 = __expf(s[j][3] - mn1);
            rs0 += p0 + p1; rs1 += p2 + p3;
            int col = j * 8 + 2 * tg;
            __half2 hp0 = __floats2half2_rn(p0, p1);
            __half2 hp1 = __floats2half2_rn(p2, p3);
            *(unsigned*)&Ps[(mw + g) * 72 + col] = h2u(hp0);
            *(unsigned*)&Ps[(mw + g + 8) * 72 + col] = h2u(hp1);
        }
        rs0 += __shfl_xor_sync(0xffffffffu, rs0, 1);
        rs0 += __shfl_xor_sync(0xffffffffu, rs0, 2);
        rs1 += __shfl_xor_sync(0xffffffffu, rs1, 1);
        rs1 += __shfl_xor_sync(0xffffffffu, rs1, 2);
        l0 = l0 * al0 + rs0;
        l1 = l1 * al1 + rs1;
#pragma unroll
        for (int j = 0; j < 8; j++) {
            O[j][0] *= al0; O[j][1] *= al0; O[j][2] *= al1; O[j][3] *= al1;
        }
        __syncwarp();   // P frags (warp-local rows) visible

        // O += P @ V  (V natural [token][dim] -> ldmatrix.x2.trans for B)
#pragma unroll
        for (int k16 = 0; k16 < 4; k16++) {
            int kk = k16 * 16;
            unsigned a0 = *(const unsigned*)&Ps[(mw + g) * 72 + kk + 2 * tg];
            unsigned a1 = *(const unsigned*)&Ps[(mw + g + 8) * 72 + kk + 2 * tg];
            unsigned a2 = *(const unsigned*)&Ps[(mw + g) * 72 + kk + 2 * tg + 8];
            unsigned a3 = *(const unsigned*)&Ps[(mw + g + 8) * 72 + kk + 2 * tg + 8];
            int vrow = kk + (lane & 7) + ((lane >> 3) & 1) * 8;
#pragma unroll
            for (int j = 0; j < 8; j++) {
                unsigned b0, b1;
                unsigned saddr = (unsigned)__cvta_generic_to_shared(&Vs[vrow * 72 + j * 8]);
                asm volatile("ldmatrix.sync.aligned.m8n8.x2.trans.shared.b16 {%0,%1}, [%2];"
                             : "=r"(b0), "=r"(b1) : "r"(saddr));
                mma_f16(O[j], a0, a1, a2, a3, b0, b1);
            }
        }
    }

    float inv0 = 1.f / l0, inv1 = 1.f / l1;
    __half* og = ctx + ((size_t)(b * NQ + q0)) * Dd + h * DH;
#pragma unroll
    for (int j = 0; j < 8; j++) {
        int col = j * 8 + 2 * tg;
        __half2 h0 = __floats2half2_rn(O[j][0] * inv0, O[j][1] * inv0);
        __half2 h1 = __floats2half2_rn(O[j][2] * inv1, O[j][3] * inv1);
        *(unsigned*)&og[(size_t)(mw + g) * Dd + col] = h2u(h0);
        *(unsigned*)&og[(size_t)(mw + g + 8) * Dd + col] = h2u(h1);
    }
}

// ---------------- launch ------------------------------------------------------
extern "C" void kernel_launch(void* const* d_in, const int* in_sizes, int n_in,
                              void* d_out, int out_size) {
    const float* upd_in = (const float*)d_in[0];
    const float* emb    = (const float*)d_in[1];
    const float* mask   = (const float*)d_in[2];
    const float* Wq     = (const float*)d_in[3];
    const float* Wk     = (const float*)d_in[4];
    const float* Wv     = (const float*)d_in[5];
    const float* Wo     = (const float*)d_in[6];
    const float* W1     = (const float*)d_in[7];
    const float* b1     = (const float*)d_in[8];
    const float* W2     = (const float*)d_in[9];
    const float* b2     = (const float*)d_in[10];
    const float* sys_s  = (const float*)d_in[11];
    const float* sys_b  = (const float*)d_in[12];
    const float* eff_s  = (const float*)d_in[13];
    const float* eff_b  = (const float*)d_in[14];
    const float* in_s   = (const float*)d_in[15];
    const float* in_b   = (const float*)d_in[16];
    const float* out_s  = (const float*)d_in[17];
    const float* out_b  = (const float*)d_in[18];
    const int*   qidx   = (const int*)d_in[19];
    const int*   kidx   = (const int*)d_in[20];
    float* out = (float*)d_out;

    float *upd, *hb, *t1f, *t2;
    __half *qh, *kh, *Qh, *Kh, *Vh, *ctxh, *hh, *t1h, *WT;
    cudaGetSymbolAddress((void**)&upd,  g_upd);
    cudaGetSymbolAddress((void**)&hb,   g_hb);
    cudaGetSymbolAddress((void**)&t1f,  g_t1f);
    cudaGetSymbolAddress((void**)&t2,   g_t2);
    cudaGetSymbolAddress((void**)&qh,   g_qh);
    cudaGetSymbolAddress((void**)&kh,   g_kh);
    cudaGetSymbolAddress((void**)&Qh,   g_Qh);
    cudaGetSymbolAddress((void**)&Kh,   g_Kh);
    cudaGetSymbolAddress((void**)&Vh,   g_Vh);
    cudaGetSymbolAddress((void**)&ctxh, g_ctxh);
    cudaGetSymbolAddress((void**)&hh,   g_hh);
    cudaGetSymbolAddress((void**)&t1h,  g_t1h);
    cudaGetSymbolAddress((void**)&WT,   g_WT);

    cudaFuncSetAttribute(flash_attn, cudaFuncAttributeMaxDynamicSharedMemorySize, 55296);

    int n_upd = Bb * NS * Dd;
    k_init<<<8192, 256>>>(upd_in, upd, out, n_upd);
    k_prep<<<dim3(8, 8, 6), dim3(32, 8)>>>(Wq, Wk, Wv, Wo, W1, W2, WT);

    const int DD2 = Dd * Dd;
    for (int l = 0; l < Ll; l++) {
        const float* mask_l = mask + (size_t)l * NQ * NK;
        const int* qi = qidx + l * NQ;
        const int* ki = kidx + l * NK;

        k_gather_ln<<<Bb * NQ / 4, 256>>>(emb, upd, qi, sys_s, sys_b, qh, NQ);
        k_gather_ln<<<Bb * NK / 4, 256>>>(emb, upd, ki, sys_s, sys_b, kh, NK);

        proj_h<0, 1><<<dim3(128, 4), 256>>>(qh, WT + 0 * DD2, nullptr, Qh, nullptr);
        proj_h<0, 1><<<dim3(256, 4), 256>>>(kh, WT + 1 * DD2, nullptr, Kh, nullptr);
        proj_h<0, 1><<<dim3(256, 4), 256>>>(kh, WT + 2 * DD2, nullptr, Vh, nullptr);

        flash_attn<<<dim3(NQ / 128, 1, Bb * Hh), 256, 55296>>>(Qh, Kh, Vh, mask_l, ctxh);

        proj_h<0, 0><<<dim3(128, 4), 256>>>(ctxh, WT + 3 * DD2, nullptr, nullptr, t1f);
        k_ln<<<Bb * NQ / 4, 256>>>(t1f, in_s, in_b, hb, hh);

        proj_h<1, 1><<<dim3(128, 4), 256>>>(hh, WT + 4 * DD2, b1, t1h, nullptr);
        proj_h<0, 0><<<dim3(128, 4), 256>>>(t1h, WT + 5 * DD2, b2, nullptr, t2);

        k_dln_scatter<<<Bb * NQ / 4, 256>>>(hb, t2, out_s, out_b, eff_s, eff_b,
                                            qi, upd, out);
    }
}

// round 9
// speedup vs baseline: 2.3831x; 1.0761x over previous
#include <cuda_runtime.h>
#include <cuda_fp16.h>
#include <math.h>

#define Bb 32
#define NS 4096
#define Dd 256
#define Hh 4
#define Ll 6
#define NQ 512
#define NK 1024
#define DH 64
#define ATTN_SCALE 0.125f

// ---------------- scratch (static device globals; no allocation) -------------
__device__ float  g_upd[Bb * NS * Dd];
__device__ float  g_hb [Bb * NQ * Dd];
__device__ float  g_t1f[Bb * NQ * Dd];
__device__ float  g_t2 [Bb * NQ * Dd];
__device__ __half g_qh [Bb * NQ * Dd];
__device__ __half g_kh [Bb * NK * Dd];
__device__ __half g_Qh [Bb * NQ * Dd];
__device__ __half g_Kh [Bb * NK * Dd];
__device__ __half g_Vh [Bb * NK * Dd];
__device__ __half g_ctxh[Bb * NQ * Dd];
__device__ __half g_hh [Bb * NQ * Dd];
__device__ __half g_t1h[Bb * NQ * Dd];
__device__ __half g_WT [6 * Dd * Dd];                  // transposed half weights [n][k]
__device__ unsigned long long g_mpk[Ll * NQ * 16];     // bit-packed masks

// ---------------- helpers ----------------------------------------------------
__device__ __forceinline__ float gelu_tanh(float x) {
    float x3 = x * x * x;
    return 0.5f * x * (1.f + tanhf(0.7978845608028654f * (x + 0.044715f * x3)));
}

__device__ __forceinline__ unsigned h2u(__half2 h) {
    return *reinterpret_cast<unsigned*>(&h);
}

__device__ __forceinline__ void mma_f16(float c[4], unsigned a0, unsigned a1,
                                        unsigned a2, unsigned a3,
                                        unsigned b0, unsigned b1) {
    asm volatile(
        "mma.sync.aligned.m16n8k16.row.col.f32.f16.f16.f32 "
        "{%0,%1,%2,%3}, {%4,%5,%6,%7}, {%8,%9}, {%0,%1,%2,%3};"
        : "+f"(c[0]), "+f"(c[1]), "+f"(c[2]), "+f"(c[3])
        : "r"(a0), "r"(a1), "r"(a2), "r"(a3), "r"(b0), "r"(b1));
}

__device__ __forceinline__ float gsum64(float v, float* part, int warp, int lane, int grp) {
#pragma unroll
    for (int o = 16; o; o >>= 1) v += __shfl_xor_sync(0xffffffffu, v, o);
    if (lane == 0) part[warp] = v;
    __syncthreads();
    return part[2 * grp] + part[2 * grp + 1];
}

// ---------------- init: upd = copy(src) ---------------------------------------
__global__ void k_init(const float* __restrict__ src, float* __restrict__ upd, int n) {
    for (int i = blockIdx.x * blockDim.x + threadIdx.x; i < n; i += gridDim.x * blockDim.x)
        upd[i] = src[i];
}

// ---------------- final: out = upd - upd_in -----------------------------------
__global__ void k_final(const float* __restrict__ upd, const float* __restrict__ src,
                        float* __restrict__ out, int n) {
    for (int i = blockIdx.x * blockDim.x + threadIdx.x; i < n; i += gridDim.x * blockDim.x)
        out[i] = upd[i] - src[i];
}

// ---------------- pack masks into bits: mp[l][q][kt] --------------------------
__global__ void k_maskpack(const float* __restrict__ mask, unsigned long long* __restrict__ mp) {
    int w = blockIdx.x * blockDim.x + threadIdx.x;
    if (w >= Ll * NQ * 16) return;
    int kt = w & 15, q = (w >> 4) & (NQ - 1), l = w >> 13;
    const float* src = mask + ((size_t)l * NQ + q) * NK + kt * 64;
    unsigned long long bits = 0;
#pragma unroll
    for (int c = 0; c < 64; c += 4) {
        float4 v = *(const float4*)&src[c];
        bits |= ((unsigned long long)(v.x > 0.5f)) << c;
        bits |= ((unsigned long long)(v.y > 0.5f)) << (c + 1);
        bits |= ((unsigned long long)(v.z > 0.5f)) << (c + 2);
        bits |= ((unsigned long long)(v.w > 0.5f)) << (c + 3);
    }
    mp[w] = bits;
}

// ---------------- weight transpose + fp16 convert (once per launch) -----------
__global__ void k_prep(const float* __restrict__ Wq, const float* __restrict__ Wk,
                       const float* __restrict__ Wv, const float* __restrict__ Wo,
                       const float* __restrict__ W1, const float* __restrict__ W2,
                       __half* __restrict__ WT) {
    __shared__ float tile[32][33];
    int w = blockIdx.z;
    const float* W = (w == 0) ? Wq : (w == 1) ? Wk : (w == 2) ? Wv
                   : (w == 3) ? Wo : (w == 4) ? W1 : W2;
    int k0 = blockIdx.x * 32, n0 = blockIdx.y * 32;
    int tx = threadIdx.x, ty = threadIdx.y;
#pragma unroll
    for (int r = 0; r < 32; r += 8)
        tile[ty + r][tx] = W[(size_t)(k0 + ty + r) * Dd + n0 + tx];
    __syncthreads();
#pragma unroll
    for (int r = 0; r < 32; r += 8)
        WT[(size_t)w * Dd * Dd + (size_t)(n0 + ty + r) * Dd + k0 + tx] =
            __float2half(tile[tx][ty + r]);
}

// ---------------- gather + layernorm -> half ----------------------------------
__global__ void k_gather_ln(const float* __restrict__ emb, const float* __restrict__ upd,
                            const int* __restrict__ idx, const float* __restrict__ sc,
                            const float* __restrict__ bi, __half* __restrict__ out, int NR) {
    __shared__ float p1[8], p2[8];
    int tid = threadIdx.x, grp = tid >> 6, t = tid & 63, warp = tid >> 5, lane = tid & 31;
    int row = blockIdx.x * 4 + grp;
    int b = row / NR, i = row - b * NR;
    int id = idx[i];
    float4 e = ((const float4*)(emb + (size_t)id * Dd))[t];
    float4 u = ((const float4*)(upd + ((size_t)b * NS + id) * Dd))[t];
    float4 x = make_float4(e.x + u.x, e.y + u.y, e.z + u.z, e.w + u.w);
    float m = gsum64(x.x + x.y + x.z + x.w, p1, warp, lane, grp) * (1.f / 256.f);
    float4 dv = make_float4(x.x - m, x.y - m, x.z - m, x.w - m);
    float var = gsum64(dv.x * dv.x + dv.y * dv.y + dv.z * dv.z + dv.w * dv.w,
                       p2, warp, lane, grp) * (1.f / 256.f);
    float rs = rsqrtf(var + 1e-5f);
    float4 s4 = ((const float4*)sc)[t];
    float4 b4 = ((const float4*)bi)[t];
    __half2 h0 = __floats2half2_rn(dv.x * rs * s4.x + b4.x, dv.y * rs * s4.y + b4.y);
    __half2 h1 = __floats2half2_rn(dv.z * rs * s4.z + b4.z, dv.w * rs * s4.w + b4.w);
    uint2 pk; pk.x = h2u(h0); pk.y = h2u(h1);
    *(uint2*)&out[(size_t)row * Dd + 4 * t] = pk;
}

// ---------------- layernorm -> fp32 + half ------------------------------------
__global__ void k_ln(const float* __restrict__ x, const float* __restrict__ sc,
                     const float* __restrict__ bi, float* __restrict__ outf,
                     __half* __restrict__ outh) {
    __shared__ float p1[8], p2[8];
    int tid = threadIdx.x, grp = tid >> 6, t = tid & 63, warp = tid >> 5, lane = tid & 31;
    size_t row = blockIdx.x * 4 + grp;
    float4 v = ((const float4*)(x + row * Dd))[t];
    float m = gsum64(v.x + v.y + v.z + v.w, p1, warp, lane, grp) * (1.f / 256.f);
    float4 dv = make_float4(v.x - m, v.y - m, v.z - m, v.w - m);
    float var = gsum64(dv.x * dv.x + dv.y * dv.y + dv.z * dv.z + dv.w * dv.w,
                       p2, warp, lane, grp) * (1.f / 256.f);
    float rs = rsqrtf(var + 1e-5f);
    float4 s4 = ((const float4*)sc)[t];
    float4 b4 = ((const float4*)bi)[t];
    float4 y = make_float4(dv.x * rs * s4.x + b4.x, dv.y * rs * s4.y + b4.y,
                           dv.z * rs * s4.z + b4.z, dv.w * rs * s4.w + b4.w);
    ((float4*)(outf + row * Dd))[t] = y;
    __half2 h0 = __floats2half2_rn(y.x, y.y);
    __half2 h1 = __floats2half2_rn(y.z, y.w);
    uint2 pk; pk.x = h2u(h0); pk.y = h2u(h1);
    *(uint2*)&outh[row * Dd + 4 * t] = pk;
}

// ---------------- fused double-LN + scatter-add (upd only) --------------------
__global__ void k_dln_scatter(const float* __restrict__ hb, const float* __restrict__ f,
                              const float* __restrict__ os, const float* __restrict__ ob,
                              const float* __restrict__ es, const float* __restrict__ eb,
                              const int* __restrict__ qi, float* __restrict__ upd) {
    __shared__ float p1[8], p2[8], p3[8], p4[8];
    int tid = threadIdx.x, grp = tid >> 6, t = tid & 63, warp = tid >> 5, lane = tid & 31;
    int row = blockIdx.x * 4 + grp;
    int b = row / NQ, q = row - b * NQ;
    float4 hv = ((const float4*)(hb + (size_t)row * Dd))[t];
    float4 fv = ((const float4*)(f + (size_t)row * Dd))[t];
    float4 x = make_float4(hv.x + fv.x, hv.y + fv.y, hv.z + fv.z, hv.w + fv.w);
    float m = gsum64(x.x + x.y + x.z + x.w, p1, warp, lane, grp) * (1.f / 256.f);
    float4 dv = make_float4(x.x - m, x.y - m, x.z - m, x.w - m);
    float var = gsum64(dv.x * dv.x + dv.y * dv.y + dv.z * dv.z + dv.w * dv.w,
                       p2, warp, lane, grp) * (1.f / 256.f);
    float rs = rsqrtf(var + 1e-5f);
    float4 s4 = ((const float4*)os)[t];
    float4 b4 = ((const float4*)ob)[t];
    float4 y = make_float4(dv.x * rs * s4.x + b4.x, dv.y * rs * s4.y + b4.y,
                           dv.z * rs * s4.z + b4.z, dv.w * rs * s4.w + b4.w);
    m = gsum64(y.x + y.y + y.z + y.w, p3, warp, lane, grp) * (1.f / 256.f);
    dv = make_float4(y.x - m, y.y - m, y.z - m, y.w - m);
    var = gsum64(dv.x * dv.x + dv.y * dv.y + dv.z * dv.z + dv.w * dv.w,
                 p4, warp, lane, grp) * (1.f / 256.f);
    rs = rsqrtf(var + 1e-5f);
    s4 = ((const float4*)es)[t];
    b4 = ((const float4*)eb)[t];
    float r0 = dv.x * rs * s4.x + b4.x, r1 = dv.y * rs * s4.y + b4.y;
    float r2 = dv.z * rs * s4.z + b4.z, r3 = dv.w * rs * s4.w + b4.w;
    int id = qi[q];
    size_t o = ((size_t)b * NS + id) * Dd + t * 4;
    atomicAdd(&upd[o + 0], r0);
    atomicAdd(&upd[o + 1], r1);
    atomicAdd(&upd[o + 2], r2);
    atomicAdd(&upd[o + 3], r3);
}

// ---------------- fp16 MMA GEMM: C = act(A @ WT^T + bias) ---------------------
template <int ACT, int HOUT>
__global__ void __launch_bounds__(256)
proj_h(const __half* __restrict__ A, const __half* __restrict__ WT,
       const float* __restrict__ bias, __half* __restrict__ Ch,
       float* __restrict__ Cf) {
    __shared__ __align__(16) __half As[128 * 72];
    __shared__ __align__(16) __half Ws[64 * 72];
    int m0 = blockIdx.x * 128, n0 = blockIdx.y * 64;
    int tid = threadIdx.x, warp = tid >> 5, lane = tid & 31;
    int g = lane >> 2, tg = lane & 3;
    int mw = warp * 16;
    float acc[8][4];
#pragma unroll
    for (int j = 0; j < 8; j++)
#pragma unroll
        for (int i = 0; i < 4; i++) acc[j][i] = 0.f;

    for (int kc = 0; kc < 256; kc += 64) {
        __syncthreads();
#pragma unroll
        for (int it = 0; it < 4; it++) {
            int i = tid + it * 256;
            int r = i >> 3, c8 = (i & 7) << 3;
            *(uint4*)&As[r * 72 + c8] = *(const uint4*)&A[(size_t)(m0 + r) * Dd + kc + c8];
        }
#pragma unroll
        for (int it = 0; it < 2; it++) {
            int i = tid + it * 256;
            int r = i >> 3, c8 = (i & 7) << 3;
            *(uint4*)&Ws[r * 72 + c8] = *(const uint4*)&WT[(size_t)(n0 + r) * Dd + kc + c8];
        }
        __syncthreads();
#pragma unroll
        for (int k16 = 0; k16 < 4; k16++) {
            int kk = k16 * 16;
            unsigned a0 = *(const unsigned*)&As[(mw + g) * 72 + kk + 2 * tg];
            unsigned a1 = *(const unsigned*)&As[(mw + g + 8) * 72 + kk + 2 * tg];
            unsigned a2 = *(const unsigned*)&As[(mw + g) * 72 + kk + 2 * tg + 8];
            unsigned a3 = *(const unsigned*)&As[(mw + g + 8) * 72 + kk + 2 * tg + 8];
#pragma unroll
            for (int j = 0; j < 8; j++) {
                unsigned b0 = *(const unsigned*)&Ws[(j * 8 + g) * 72 + kk + 2 * tg];
                unsigned b1 = *(const unsigned*)&Ws[(j * 8 + g) * 72 + kk + 2 * tg + 8];
                mma_f16(acc[j], a0, a1, a2, a3, b0, b1);
            }
        }
    }
#pragma unroll
    for (int j = 0; j < 8; j++) {
        int col = n0 + j * 8 + 2 * tg;
        float bv0 = bias ? bias[col] : 0.f;
        float bv1 = bias ? bias[col + 1] : 0.f;
        float v0 = acc[j][0] + bv0, v1 = acc[j][1] + bv1;
        float v2 = acc[j][2] + bv0, v3 = acc[j][3] + bv1;
        if (ACT) { v0 = gelu_tanh(v0); v1 = gelu_tanh(v1); v2 = gelu_tanh(v2); v3 = gelu_tanh(v3); }
        int r0 = m0 + mw + g;
        if (HOUT) {
            __half2 hA = __floats2half2_rn(v0, v1);
            __half2 hB = __floats2half2_rn(v2, v3);
            *(unsigned*)&Ch[(size_t)r0 * Dd + col] = h2u(hA);
            *(unsigned*)&Ch[(size_t)(r0 + 8) * Dd + col] = h2u(hB);
        } else {
            *(float2*)&Cf[(size_t)r0 * Dd + col] = make_float2(v0, v1);
            *(float2*)&Cf[(size_t)(r0 + 8) * Dd + col] = make_float2(v2, v3);
        }
    }
}

// ---------------- fused flash attention (fp16 MMA, bitmask, online softmax) ---
__global__ void __launch_bounds__(256)
flash_attn(const __half* __restrict__ Q, const __half* __restrict__ K,
           const __half* __restrict__ V, const unsigned long long* __restrict__ mpk,
           __half* __restrict__ ctx) {
    extern __shared__ __half hsm[];
    __half* Qs = hsm;                // 128*72
    __half* Ks = hsm + 9216;         // 64*72
    __half* Vs = hsm + 13824;        // 64*72
    __half* Ps = hsm + 18432;        // 128*72

    int bh = blockIdx.z;
    int b = bh >> 2, h = bh & 3;
    int q0 = blockIdx.x * 128;
    int tid = threadIdx.x, warp = tid >> 5, lane = tid & 31;
    int g = lane >> 2, tg = lane & 3;
    int mw = warp * 16;

    const __half* Qg = Q + ((size_t)(b * NQ + q0)) * Dd + h * DH;
    const __half* Kg = K + ((size_t)b * NK) * Dd + h * DH;
    const __half* Vg = V + ((size_t)b * NK) * Dd + h * DH;

#pragma unroll
    for (int it = 0; it < 4; it++) {
        int i = tid + it * 256;
        int r = i >> 3, c8 = (i & 7) << 3;
        *(uint4*)&Qs[r * 72 + c8] = *(const uint4*)&Qg[(size_t)r * Dd + c8];
    }

    float O[8][4];
#pragma unroll
    for (int j = 0; j < 8; j++)
#pragma unroll
        for (int i = 0; i < 4; i++) O[j][i] = 0.f;
    float m0r = -3.0e38f, m1r = -3.0e38f, l0 = 0.f, l1 = 0.f;

    const unsigned long long* mp0 = mpk + (size_t)(q0 + mw + g) * 16;
    const unsigned long long* mp1 = mpk + (size_t)(q0 + mw + g + 8) * 16;

    for (int kt = 0; kt < 16; kt++) {
        __syncthreads();
        int kbase = kt * 64;
#pragma unroll
        for (int it = 0; it < 2; it++) {
            int i = tid + it * 256;
            int r = i >> 3, c8 = (i & 7) << 3;
            *(uint4*)&Ks[r * 72 + c8] = *(const uint4*)&Kg[(size_t)(kbase + r) * Dd + c8];
        }
#pragma unroll
        for (int it = 0; it < 2; it++) {
            int i = tid + it * 256;
            int r = i >> 3, c8 = (i & 7) << 3;
            *(uint4*)&Vs[r * 72 + c8] = *(const uint4*)&Vg[(size_t)(kbase + r) * Dd + c8];
        }
        unsigned long long mb0 = mp0[kt];
        unsigned long long mb1 = mp1[kt];
        __syncthreads();

        // S = Q @ K^T
        float s[8][4];
#pragma unroll
        for (int j = 0; j < 8; j++)
#pragma unroll
            for (int i = 0; i < 4; i++) s[j][i] = 0.f;
#pragma unroll
        for (int k16 = 0; k16 < 4; k16++) {
            int kk = k16 * 16;
            unsigned a0 = *(const unsigned*)&Qs[(mw + g) * 72 + kk + 2 * tg];
            unsigned a1 = *(const unsigned*)&Qs[(mw + g + 8) * 72 + kk + 2 * tg];
            unsigned a2 = *(const unsigned*)&Qs[(mw + g) * 72 + kk + 2 * tg + 8];
            unsigned a3 = *(const unsigned*)&Qs[(mw + g + 8) * 72 + kk + 2 * tg + 8];
#pragma unroll
            for (int j = 0; j < 8; j++) {
                unsigned b0 = *(const unsigned*)&Ks[(j * 8 + g) * 72 + kk + 2 * tg];
                unsigned b1 = *(const unsigned*)&Ks[(j * 8 + g) * 72 + kk + 2 * tg + 8];
                mma_f16(s[j], a0, a1, a2, a3, b0, b1);
            }
        }

        // scale + bitmask + row max
        float mx0 = -3.0e38f, mx1 = -3.0e38f;
#pragma unroll
        for (int j = 0; j < 8; j++) {
            int c = j * 8 + 2 * tg;
            s[j][0] = ((mb0 >> c) & 1ull) ? s[j][0] * ATTN_SCALE : -1e9f;
            s[j][1] = ((mb0 >> (c + 1)) & 1ull) ? s[j][1] * ATTN_SCALE : -1e9f;
            s[j][2] = ((mb1 >> c) & 1ull) ? s[j][2] * ATTN_SCALE : -1e9f;
            s[j][3] = ((mb1 >> (c + 1)) & 1ull) ? s[j][3] * ATTN_SCALE : -1e9f;
            mx0 = fmaxf(mx0, fmaxf(s[j][0], s[j][1]));
            mx1 = fmaxf(mx1, fmaxf(s[j][2], s[j][3]));
        }
        mx0 = fmaxf(mx0, __shfl_xor_sync(0xffffffffu, mx0, 1));
        mx0 = fmaxf(mx0, __shfl_xor_sync(0xffffffffu, mx0, 2));
        mx1 = fmaxf(mx1, __shfl_xor_sync(0xffffffffu, mx1, 1));
        mx1 = fmaxf(mx1, __shfl_xor_sync(0xffffffffu, mx1, 2));

        float mn0 = fmaxf(m0r, mx0), mn1 = fmaxf(m1r, mx1);
        float al0 = __expf(m0r - mn0), al1 = __expf(m1r - mn1);
        m0r = mn0; m1r = mn1;

        float rs0 = 0.f, rs1 = 0.f;
#pragma unroll
        for (int j = 0; j < 8; j++) {
            float p0 = __expf(s[j][0] - mn0), p1 = __expf(s[j][1] - mn0);
            float p2 = __expf(s[j][2] - mn1), p3 = __expf(s[j][3] - mn1);
            rs0 += p0 + p1; rs1 += p2 + p3;
            int col = j * 8 + 2 * tg;
            __half2 hp0 = __floats2half2_rn(p0, p1);
            __half2 hp1 = __floats2half2_rn(p2, p3);
            *(unsigned*)&Ps[(mw + g) * 72 + col] = h2u(hp0);
            *(unsigned*)&Ps[(mw + g + 8) * 72 + col] = h2u(hp1);
        }
        rs0 += __shfl_xor_sync(0xffffffffu, rs0, 1);
        rs0 += __shfl_xor_sync(0xffffffffu, rs0, 2);
        rs1 += __shfl_xor_sync(0xffffffffu, rs1, 1);
        rs1 += __shfl_xor_sync(0xffffffffu, rs1, 2);
        l0 = l0 * al0 + rs0;
        l1 = l1 * al1 + rs1;
#pragma unroll
        for (int j = 0; j < 8; j++) {
            O[j][0] *= al0; O[j][1] *= al0; O[j][2] *= al1; O[j][3] *= al1;
        }
        __syncwarp();

        // O += P @ V
#pragma unroll
        for (int k16 = 0; k16 < 4; k16++) {
            int kk = k16 * 16;
            unsigned a0 = *(const unsigned*)&Ps[(mw + g) * 72 + kk + 2 * tg];
            unsigned a1 = *(const unsigned*)&Ps[(mw + g + 8) * 72 + kk + 2 * tg];
            unsigned a2 = *(const unsigned*)&Ps[(mw + g) * 72 + kk + 2 * tg + 8];
            unsigned a3 = *(const unsigned*)&Ps[(mw + g + 8) * 72 + kk + 2 * tg + 8];
            int vrow = kk + (lane & 7) + ((lane >> 3) & 1) * 8;
#pragma unroll
            for (int j = 0; j < 8; j++) {
                unsigned b0, b1;
                unsigned saddr = (unsigned)__cvta_generic_to_shared(&Vs[vrow * 72 + j * 8]);
                asm volatile("ldmatrix.sync.aligned.m8n8.x2.trans.shared.b16 {%0,%1}, [%2];"
                             : "=r"(b0), "=r"(b1) : "r"(saddr));
                mma_f16(O[j], a0, a1, a2, a3, b0, b1);
            }
        }
    }

    float inv0 = 1.f / l0, inv1 = 1.f / l1;
    __half* og = ctx + ((size_t)(b * NQ + q0)) * Dd + h * DH;
#pragma unroll
    for (int j = 0; j < 8; j++) {
        int col = j * 8 + 2 * tg;
        __half2 h0 = __floats2half2_rn(O[j][0] * inv0, O[j][1] * inv0);
        __half2 h1 = __floats2half2_rn(O[j][2] * inv1, O[j][3] * inv1);
        *(unsigned*)&og[(size_t)(mw + g) * Dd + col] = h2u(h0);
        *(unsigned*)&og[(size_t)(mw + g + 8) * Dd + col] = h2u(h1);
    }
}

// ---------------- launch ------------------------------------------------------
extern "C" void kernel_launch(void* const* d_in, const int* in_sizes, int n_in,
                              void* d_out, int out_size) {
    const float* upd_in = (const float*)d_in[0];
    const float* emb    = (const float*)d_in[1];
    const float* mask   = (const float*)d_in[2];
    const float* Wq     = (const float*)d_in[3];
    const float* Wk     = (const float*)d_in[4];
    const float* Wv     = (const float*)d_in[5];
    const float* Wo     = (const float*)d_in[6];
    const float* W1     = (const float*)d_in[7];
    const float* b1     = (const float*)d_in[8];
    const float* W2     = (const float*)d_in[9];
    const float* b2     = (const float*)d_in[10];
    const float* sys_s  = (const float*)d_in[11];
    const float* sys_b  = (const float*)d_in[12];
    const float* eff_s  = (const float*)d_in[13];
    const float* eff_b  = (const float*)d_in[14];
    const float* in_s   = (const float*)d_in[15];
    const float* in_b   = (const float*)d_in[16];
    const float* out_s  = (const float*)d_in[17];
    const float* out_b  = (const float*)d_in[18];
    const int*   qidx   = (const int*)d_in[19];
    const int*   kidx   = (const int*)d_in[20];
    float* out = (float*)d_out;

    float *upd, *hb, *t1f, *t2;
    __half *qh, *kh, *Qh, *Kh, *Vh, *ctxh, *hh, *t1h, *WT;
    unsigned long long* mpk;
    cudaGetSymbolAddress((void**)&upd,  g_upd);
    cudaGetSymbolAddress((void**)&hb,   g_hb);
    cudaGetSymbolAddress((void**)&t1f,  g_t1f);
    cudaGetSymbolAddress((void**)&t2,   g_t2);
    cudaGetSymbolAddress((void**)&qh,   g_qh);
    cudaGetSymbolAddress((void**)&kh,   g_kh);
    cudaGetSymbolAddress((void**)&Qh,   g_Qh);
    cudaGetSymbolAddress((void**)&Kh,   g_Kh);
    cudaGetSymbolAddress((void**)&Vh,   g_Vh);
    cudaGetSymbolAddress((void**)&ctxh, g_ctxh);
    cudaGetSymbolAddress((void**)&hh,   g_hh);
    cudaGetSymbolAddress((void**)&t1h,  g_t1h);
    cudaGetSymbolAddress((void**)&WT,   g_WT);
    cudaGetSymbolAddress((void**)&mpk,  g_mpk);

    cudaFuncSetAttribute(flash_attn, cudaFuncAttributeMaxDynamicSharedMemorySize, 55296);

    int n_upd = Bb * NS * Dd;
    k_init<<<8192, 256>>>(upd_in, upd, n_upd);
    k_prep<<<dim3(8, 8, 6), dim3(32, 8)>>>(Wq, Wk, Wv, Wo, W1, W2, WT);
    k_maskpack<<<(Ll * NQ * 16 + 255) / 256, 256>>>(mask, mpk);

    const int DD2 = Dd * Dd;
    for (int l = 0; l < Ll; l++) {
        const unsigned long long* mpk_l = mpk + (size_t)l * NQ * 16;
        const int* qi = qidx + l * NQ;
        const int* ki = kidx + l * NK;

        k_gather_ln<<<Bb * NQ / 4, 256>>>(emb, upd, qi, sys_s, sys_b, qh, NQ);
        k_gather_ln<<<Bb * NK / 4, 256>>>(emb, upd, ki, sys_s, sys_b, kh, NK);

        proj_h<0, 1><<<dim3(128, 4), 256>>>(qh, WT + 0 * DD2, nullptr, Qh, nullptr);
        proj_h<0, 1><<<dim3(256, 4), 256>>>(kh, WT + 1 * DD2, nullptr, Kh, nullptr);
        proj_h<0, 1><<<dim3(256, 4), 256>>>(kh, WT + 2 * DD2, nullptr, Vh, nullptr);

        flash_attn<<<dim3(NQ / 128, 1, Bb * Hh), 256, 55296>>>(Qh, Kh, Vh, mpk_l, ctxh);

        proj_h<0, 0><<<dim3(128, 4), 256>>>(ctxh, WT + 3 * DD2, nullptr, nullptr, t1f);
        k_ln<<<Bb * NQ / 4, 256>>>(t1f, in_s, in_b, hb, hh);

        proj_h<1, 1><<<dim3(128, 4), 256>>>(hh, WT + 4 * DD2, b1, t1h, nullptr);
        proj_h<0, 0><<<dim3(128, 4), 256>>>(t1h, WT + 5 * DD2, b2, nullptr, t2);

        k_dln_scatter<<<Bb * NQ / 4, 256>>>(hb, t2, out_s, out_b, eff_s, eff_b, qi, upd);
    }
    k_final<<<8192, 256>>>(upd, upd_in, out, n_upd);
}